// round 13
// baseline (speedup 1.0000x reference)
#include <cuda_runtime.h>
#include <cuda_fp16.h>
#include <math.h>
#include <stdint.h>

// Problem constants
#define kE   2048
#define kHQ  32
#define kHKV 8
#define kHD  64
#define kB   2
#define kT   2048
#define kM   (kB * kT)          // 4096 rows (B*T)
#define kKVN (2 * kHKV * kHD)   // 1024

#define QSCALE 0.1803368801111204f   // 0.125 * log2(e)

// ---------------------------------------------------------------------------
// Device-global scratch
// ---------------------------------------------------------------------------
__device__ __half g_qh[kM * kE];     // q projection, fp16, pre-scaled by QSCALE
__device__ __half g_kvh[kM * kKVN];  // kv projection fp16: k [0,512), v [512,1024)
__device__ __half g_xh[kM * kE];
__device__ __half g_wqh[kE * kE];
__device__ __half g_wkvh[kKVN * kE];
__device__ __half g_woh[kE * kE];
__device__ __half g_aoh[kM * kE];    // attention out, fp16

// ---------------------------------------------------------------------------
// Helpers
// ---------------------------------------------------------------------------
__device__ __forceinline__ uint32_t smem_u32(const void* p) {
    uint32_t a;
    asm("{ .reg .u64 t; cvta.to.shared.u64 t, %1; cvt.u32.u64 %0, t; }"
        : "=r"(a) : "l"(p));
    return a;
}

__device__ __forceinline__ void cp16(uint32_t saddr, const void* g) {
    asm volatile("cp.async.cg.shared.global [%0], [%1], 16;"
                 :: "r"(saddr), "l"(g) : "memory");
}
#define CP_COMMIT()  asm volatile("cp.async.commit_group;" ::: "memory")
#define CP_WAIT(n)   asm volatile("cp.async.wait_group %0;" :: "n"(n) : "memory")

#define LDSM4(r, addr)                                                        \
    asm volatile("ldmatrix.sync.aligned.m8n8.x4.shared.b16 {%0,%1,%2,%3}, [%4];" \
        : "=r"((r)[0]), "=r"((r)[1]), "=r"((r)[2]), "=r"((r)[3]) : "r"(addr))

#define LDSM4T(r, addr)                                                       \
    asm volatile("ldmatrix.sync.aligned.m8n8.x4.trans.shared.b16 {%0,%1,%2,%3}, [%4];" \
        : "=r"((r)[0]), "=r"((r)[1]), "=r"((r)[2]), "=r"((r)[3]) : "r"(addr))

// fp16 tensor op: D(16x8,f32) += A(16x16,f16) * B(16x8,f16)
__device__ __forceinline__ void mma_fp16(float* d, const uint32_t* a, const uint32_t* b) {
    asm volatile(
        "mma.sync.aligned.m16n8k16.row.col.f32.f16.f16.f32 "
        "{%0,%1,%2,%3},{%4,%5,%6,%7},{%8,%9},{%0,%1,%2,%3};\n"
        : "+f"(d[0]), "+f"(d[1]), "+f"(d[2]), "+f"(d[3])
        : "r"(a[0]), "r"(a[1]), "r"(a[2]), "r"(a[3]), "r"(b[0]), "r"(b[1]));
}

__device__ __forceinline__ uint32_t pack_h2(float a, float b) {
    __half2 h = __floats2half2_rn(a, b);
    return *reinterpret_cast<uint32_t*>(&h);
}

__device__ __forceinline__ float ex2(float x) {
    float r;
    asm("ex2.approx.ftz.f32 %0, %1;" : "=f"(r) : "f"(x));
    return r;
}

// ---------------------------------------------------------------------------
// Fused fp32 -> fp16 cast of x, Wq, Wkv, Wo (one launch)
// ---------------------------------------------------------------------------
#define C1 2097152              // x       float4 count
#define C2 (C1 + 1048576)       // + Wq
#define C3 (C2 + 524288)        // + Wkv
#define C4 (C3 + 1048576)       // + Wo

__global__ __launch_bounds__(256) void cast_all(
        const float* __restrict__ x,  const float* __restrict__ wq,
        const float* __restrict__ wkv, const float* __restrict__ wo,
        __half* __restrict__ xh, __half* __restrict__ wqh,
        __half* __restrict__ wkvh, __half* __restrict__ woh) {
    int i = blockIdx.x * 256 + threadIdx.x;
    if (i >= C4) return;
    const float* src; __half* dst; int off;
    if (i < C1)      { src = x;   dst = xh;   off = i; }
    else if (i < C2) { src = wq;  dst = wqh;  off = i - C1; }
    else if (i < C3) { src = wkv; dst = wkvh; off = i - C2; }
    else             { src = wo;  dst = woh;  off = i - C3; }
    float4 v = ((const float4*)src)[off];
    uint32_t* hp = (uint32_t*)dst;
    hp[2*off]   = pack_h2(v.x, v.y);
    hp[2*off+1] = pack_h2(v.z, v.w);
}

// ---------------------------------------------------------------------------
// GEMM: C[M,N] = scale * A[M,K] * W[N,K]^T, plain fp16.
// CTA 128x128, K-tile 64 (one barrier per k-tile), 8 warps, 2-stage cp.async.
// Row stride 144B (== 4 mod 32 words): conflict-free LDSM.
// ---------------------------------------------------------------------------
#define SPLANE_B 18432                      // 128 rows * 144B
#define STAGE_B  (2 * SPLANE_B)             // A, W
#define GEMM_SMEM (2 * STAGE_B)             // 73728 bytes

__global__ __launch_bounds__(256) void gemm_f16(
        const __half* __restrict__ Ah, const __half* __restrict__ Whi,
        float* __restrict__ Cf, __half* __restrict__ Ch,
        float scale, int N, int K, int half_out) {
    extern __shared__ char smem[];
    const uint32_t sbase = smem_u32(smem);

    const int tid  = threadIdx.x;
    const int lane = tid & 31;
    const int wid  = tid >> 5;
    const int wm   = wid >> 1;        // 0..3
    const int wn   = wid & 1;         // 0..1
    const int m0   = blockIdx.y * 128;
    const int n0   = blockIdx.x * 128;

    float acc[2][8][4];
#pragma unroll
    for (int i = 0; i < 2; i++)
#pragma unroll
        for (int j = 0; j < 8; j++)
#pragma unroll
            for (int k = 0; k < 4; k++) acc[i][j][k] = 0.f;

    const size_t gs = (size_t)K * 2;  // bytes per global row
    const int mat  = tid >> 7;        // 0 = A, 1 = W
    const int crow = tid & 127;       // row within tile

    const char* pA = (const char*)Ah;
    const char* pW = (const char*)Whi;
    const char* gbase = (mat ? pW + (size_t)(n0 + crow) * gs
                             : pA + (size_t)(m0 + crow) * gs);
    const uint32_t stbase = sbase + mat * SPLANE_B + crow * 144;

    const int NKT = K >> 6;

    auto copy_tile = [&](int s, int kt) {
        const char* g = gbase + (size_t)kt * 128;
        const uint32_t st = stbase + s * STAGE_B;
#pragma unroll
        for (int i = 0; i < 8; i++)
            cp16(st + i * 16, g + i * 16);
    };

    copy_tile(0, 0);
    CP_COMMIT();

    // ldmatrix lane-address components
    const int lr8 = lane & 7;
    const int r8  = (lane >> 3) & 1;
    const int c4  = (lane >> 4) & 1;
    const uint32_t aoff0 = (uint32_t)((wm * 32 + lr8 + 8 * r8) * 144 + c4 * 16);
    const uint32_t aoff1 = aoff0 + 16 * 144;
    uint32_t boff[4];
#pragma unroll
    for (int np = 0; np < 4; np++)
        boff[np] = (uint32_t)((wn * 64 + np * 16 + lr8 + 8 * r8) * 144 + c4 * 16);

    const int rq = lane >> 2;
    const int wc = lane & 3;

    for (int kt = 0; kt < NKT; kt++) {
        CP_WAIT(0);
        __syncthreads();                 // stage kt&1 ready; other stage free
        if (kt + 1 < NKT) {
            copy_tile((kt + 1) & 1, kt + 1);   // overlaps compute below
            CP_COMMIT();
        }

        const uint32_t stA = sbase + (kt & 1) * STAGE_B;
        const uint32_t stW = stA + SPLANE_B;

#pragma unroll
        for (int ks = 0; ks < 4; ks++) {
            const uint32_t ko = ks * 32;
            uint32_t ah[2][4];
            LDSM4(ah[0], stA + aoff0 + ko);
            LDSM4(ah[1], stA + aoff1 + ko);
            uint32_t bh[4][4];
#pragma unroll
            for (int np = 0; np < 4; np++)
                LDSM4(bh[np], stW + boff[np] + ko);
#pragma unroll
            for (int nt = 0; nt < 8; nt++) {
                const int np = nt >> 1, g = nt & 1;
                uint32_t bhf[2] = {bh[np][g], bh[np][2 + g]};
                mma_fp16(acc[0][nt], ah[0], bhf);
                mma_fp16(acc[1][nt], ah[1], bhf);
            }
        }
    }

    if (half_out) {
#pragma unroll
        for (int mt = 0; mt < 2; mt++) {
            const int r = m0 + wm * 32 + mt * 16 + rq;
#pragma unroll
            for (int nt = 0; nt < 8; nt++) {
                const int c = n0 + wn * 64 + nt * 8 + (wc << 1);
                *(uint32_t*)&Ch[(size_t)r * N + c] =
                    pack_h2(acc[mt][nt][0] * scale, acc[mt][nt][1] * scale);
                *(uint32_t*)&Ch[(size_t)(r + 8) * N + c] =
                    pack_h2(acc[mt][nt][2] * scale, acc[mt][nt][3] * scale);
            }
        }
    } else {
#pragma unroll
        for (int mt = 0; mt < 2; mt++) {
            const int r = m0 + wm * 32 + mt * 16 + rq;
#pragma unroll
            for (int nt = 0; nt < 8; nt++) {
                const int c = n0 + wn * 64 + nt * 8 + (wc << 1);
                *(float2*)&Cf[(size_t)r * N + c]       = make_float2(acc[mt][nt][0], acc[mt][nt][1]);
                *(float2*)&Cf[(size_t)(r + 8) * N + c] = make_float2(acc[mt][nt][2], acc[mt][nt][3]);
            }
        }
    }
}

// ---------------------------------------------------------------------------
// Flash attention (causal, GQA), fp16 m16n8k16.
// - cp.async double-buffered K/V, one barrier per kv-tile
// - V in natural [t][d] layout, B-fragments via ldmatrix.x4.trans
// - P stays in registers (C-frag == A-frag identity)
// - 2 query heads per CTA share the K/V stream; LPT launch order
// ---------------------------------------------------------------------------
#define AQ_OFF 0                         // Qs: 2 heads * 64 * 144 = 18432
#define AK_OFF 18432                     // K stages: 2 * 9216
#define AV_OFF 36864                     // V stages: 2 * 9216
#define ATTN_SMEM 55296

__global__ __launch_bounds__(256) void attn_kernel(
        const __half* __restrict__ qh, const __half* __restrict__ kvh,
        __half* __restrict__ aoh) {
    extern __shared__ char smc[];
    const uint32_t sb = smem_u32(smc);

    const int tid  = threadIdx.x;
    const int lane = tid & 31;
    const int w    = tid >> 5;          // 0..7
    const int wg   = w >> 2;            // head sub-index 0/1
    const int wl   = w & 3;             // warp within head
    const int qb   = gridDim.x - 1 - blockIdx.x;   // LPT: heavy blocks first
    const int pidx = blockIdx.y;        // (b, head-pair)
    const int b    = pidx >> 4;
    const int hp   = pidx & 15;
    const int hq   = hp * 2 + wg;
    const int hkv  = hp >> 1;

    const uint32_t qsu = sb + AQ_OFF + wg * 9216;

    // ---- Load both heads' Q tiles: pure 16B copies (fp16, pre-scaled)
    {
        const int half  = tid >> 7;               // 0/1 -> head
        const int hrow  = (tid & 127) >> 3;       // 0..15
        const int hcol  = (tid & 7) * 8;          // halves, 0..56
        const int hqh   = hp * 2 + half;
        char* Qdst = smc + AQ_OFF + half * 9216;
#pragma unroll
        for (int p = 0; p < 4; p++) {
            int row = p * 16 + hrow;
            const uint4 v = *(const uint4*)
                &qh[((size_t)(b * kT + qb * 64 + row)) * kE + hqh * kHD + hcol];
            *(uint4*)(Qdst + row * 144 + hcol * 2) = v;
        }
    }

    // K/V fill via cp.async: thread -> (row = tid>>2, 32B segment = tid&3)
    const int frow = tid >> 2;              // 0..63
    const int fsegh = (tid & 3) * 16;       // halves offset within row
    auto fill_kv = [&](int s, int j) {
        const __half* kg = kvh + ((size_t)(b * kT + j * 64 + frow)) * kKVN
                               + hkv * kHD + fsegh;
        const uint32_t stk = sb + AK_OFF + s * 9216 + frow * 144 + fsegh * 2;
        const uint32_t stv = sb + AV_OFF + s * 9216 + frow * 144 + fsegh * 2;
        cp16(stk,      kg);
        cp16(stk + 16, kg + 8);
        cp16(stv,      kg + 512);
        cp16(stv + 16, kg + 520);
    };

    float mrow0 = -INFINITY, mrow1 = -INFINITY;
    float lrow0 = 0.f, lrow1 = 0.f;
    float o[8][4];
#pragma unroll
    for (int nt = 0; nt < 8; nt++)
#pragma unroll
        for (int i = 0; i < 4; i++) o[nt][i] = 0.f;

    const int rloc = wl * 16 + (lane >> 2);   // warp's rows rloc, rloc+8 (0..63)

    // ldmatrix lane addresses
    const int lr8 = lane & 7;
    const int r8  = (lane >> 3) & 1;
    const int c4  = (lane >> 4) & 1;
    const uint32_t aoffQ = (uint32_t)((wl * 16 + lr8 + 8 * r8) * 144 + c4 * 16);
    uint32_t boffK[4];   // K: non-trans, [n][k]
#pragma unroll
    for (int np = 0; np < 4; np++)
        boffK[np] = (uint32_t)((np * 16 + lr8 + 8 * r8) * 144 + c4 * 16);
    uint32_t boffV[4];   // V: trans, [t][d]; lanes 0-7:k, 8-15:k+8, 16-23:n+8, 24-31:both
#pragma unroll
    for (int np = 0; np < 4; np++)
        boffV[np] = (uint32_t)((lr8 + 8 * r8) * 144 + (np * 16 + 8 * c4) * 2);

    const int la = lane & 3;

    fill_kv(0, 0);
    CP_COMMIT();

    for (int j = 0; j <= qb; j++) {
        CP_WAIT(0);
        __syncthreads();                 // stage j&1 ready; other stage free
        if (j < qb) {
            fill_kv((j + 1) & 1, j + 1); // overlaps compute below
            CP_COMMIT();
        }

        const uint32_t ksu = sb + AK_OFF + (j & 1) * 9216;
        const uint32_t vsu = sb + AV_OFF + (j & 1) * 9216;

        // S = Q * K^T  (fp16 m16n8k16, 4 k-steps)
        float s[8][4];
#pragma unroll
        for (int nt = 0; nt < 8; nt++) { s[nt][0] = s[nt][1] = s[nt][2] = s[nt][3] = 0.f; }

#pragma unroll
        for (int ks = 0; ks < 4; ks++) {
            const uint32_t ko = ks * 32;
            uint32_t a[4];
            LDSM4(a, qsu + aoffQ + ko);
#pragma unroll
            for (int np = 0; np < 4; np++) {
                uint32_t kb[4];
                LDSM4(kb, ksu + boffK[np] + ko);
#pragma unroll
                for (int g = 0; g < 2; g++) {
                    uint32_t bb[2] = {kb[g], kb[2 + g]};
                    mma_fp16(s[2 * np + g], a, bb);
                }
            }
        }

        // Causal mask on the diagonal block
        if (j == qb) {
#pragma unroll
            for (int nt = 0; nt < 8; nt++) {
                int c0 = nt * 8 + (la << 1);
                if (c0     > rloc)     s[nt][0] = -INFINITY;
                if (c0 + 1 > rloc)     s[nt][1] = -INFINITY;
                if (c0     > rloc + 8) s[nt][2] = -INFINITY;
                if (c0 + 1 > rloc + 8) s[nt][3] = -INFINITY;
            }
        }

        // Online softmax (exp2 domain)
        float mx0 = -INFINITY, mx1 = -INFINITY;
#pragma unroll
        for (int nt = 0; nt < 8; nt++) {
            mx0 = fmaxf(mx0, fmaxf(s[nt][0], s[nt][1]));
            mx1 = fmaxf(mx1, fmaxf(s[nt][2], s[nt][3]));
        }
        mx0 = fmaxf(mx0, __shfl_xor_sync(0xffffffffu, mx0, 1));
        mx0 = fmaxf(mx0, __shfl_xor_sync(0xffffffffu, mx0, 2));
        mx1 = fmaxf(mx1, __shfl_xor_sync(0xffffffffu, mx1, 1));
        mx1 = fmaxf(mx1, __shfl_xor_sync(0xffffffffu, mx1, 2));

        float mnew0 = fmaxf(mrow0, mx0);
        float mnew1 = fmaxf(mrow1, mx1);
        float alpha0 = ex2(mrow0 - mnew0);
        float alpha1 = ex2(mrow1 - mnew1);
        mrow0 = mnew0; mrow1 = mnew1;

        float sum0 = 0.f, sum1 = 0.f;
#pragma unroll
        for (int nt = 0; nt < 8; nt++) {
            s[nt][0] = ex2(s[nt][0] - mnew0); sum0 += s[nt][0];
            s[nt][1] = ex2(s[nt][1] - mnew0); sum0 += s[nt][1];
            s[nt][2] = ex2(s[nt][2] - mnew1); sum1 += s[nt][2];
            s[nt][3] = ex2(s[nt][3] - mnew1); sum1 += s[nt][3];
        }
        sum0 += __shfl_xor_sync(0xffffffffu, sum0, 1);
        sum0 += __shfl_xor_sync(0xffffffffu, sum0, 2);
        sum1 += __shfl_xor_sync(0xffffffffu, sum1, 1);
        sum1 += __shfl_xor_sync(0xffffffffu, sum1, 2);

        lrow0 = lrow0 * alpha0 + sum0;
        lrow1 = lrow1 * alpha1 + sum1;

#pragma unroll
        for (int nt = 0; nt < 8; nt++) {
            o[nt][0] *= alpha0; o[nt][1] *= alpha0;
            o[nt][2] *= alpha1; o[nt][3] *= alpha1;
        }

        // O += P * V — P packed from S registers; V B-frags via ldmatrix.trans
#pragma unroll
        for (int ks = 0; ks < 4; ks++) {
            uint32_t a[4];
            a[0] = pack_h2(s[2*ks][0],   s[2*ks][1]);
            a[1] = pack_h2(s[2*ks][2],   s[2*ks][3]);
            a[2] = pack_h2(s[2*ks+1][0], s[2*ks+1][1]);
            a[3] = pack_h2(s[2*ks+1][2], s[2*ks+1][3]);
            const uint32_t vk = vsu + ks * 16 * 144;
#pragma unroll
            for (int np = 0; np < 4; np++) {
                uint32_t vb[4];
                LDSM4T(vb, vk + boffV[np]);
                mma_fp16(o[2 * np],     a, vb);       // n-block np*16..+7
                mma_fp16(o[2 * np + 1], a, vb + 2);   // n-block np*16+8..+15
            }
        }
        // no trailing barrier: top-of-loop barrier guards stage recycling
    }

    // Normalize and emit fp16 plane for the O-projection
    float inv0 = 1.f / lrow0;
    float inv1 = 1.f / lrow1;
    size_t r0 = (size_t)(b * kT + qb * 64 + rloc) * kE + hq * kHD;
    size_t r1 = (size_t)(b * kT + qb * 64 + rloc + 8) * kE + hq * kHD;
#pragma unroll
    for (int nt = 0; nt < 8; nt++) {
        int c = nt * 8 + (la << 1);
        *(uint32_t*)&aoh[r0 + c] = pack_h2(o[nt][0] * inv0, o[nt][1] * inv0);
        *(uint32_t*)&aoh[r1 + c] = pack_h2(o[nt][2] * inv1, o[nt][3] * inv1);
    }
}

// ---------------------------------------------------------------------------
// Launch
// ---------------------------------------------------------------------------
extern "C" void kernel_launch(void* const* d_in, const int* in_sizes, int n_in,
                              void* d_out, int out_size) {
    (void)in_sizes; (void)n_in; (void)out_size;
    const float* x   = (const float*)d_in[0];
    const float* Wq  = (const float*)d_in[1];
    const float* Wkv = (const float*)d_in[2];
    const float* Wo  = (const float*)d_in[3];
    float* out = (float*)d_out;

    __half *qh, *kvh, *xh, *wqh, *wkvh, *woh, *aoh;
    cudaGetSymbolAddress((void**)&qh,   g_qh);
    cudaGetSymbolAddress((void**)&kvh,  g_kvh);
    cudaGetSymbolAddress((void**)&xh,   g_xh);
    cudaGetSymbolAddress((void**)&wqh,  g_wqh);
    cudaGetSymbolAddress((void**)&wkvh, g_wkvh);
    cudaGetSymbolAddress((void**)&woh,  g_woh);
    cudaGetSymbolAddress((void**)&aoh,  g_aoh);

    cudaFuncSetAttribute(gemm_f16,
                         cudaFuncAttributeMaxDynamicSharedMemorySize, GEMM_SMEM);
    cudaFuncSetAttribute(attn_kernel,
                         cudaFuncAttributeMaxDynamicSharedMemorySize, ATTN_SMEM);

    // One fused cast launch (x, Wq, Wkv, Wo -> fp16)
    cast_all<<<(C4 + 255) / 256, 256>>>(x, Wq, Wkv, Wo, xh, wqh, wkvh, woh);

    // Projections: plain fp16 GEMMs; q/kv emit fp16 (q pre-scaled for exp2)
    gemm_f16<<<dim3(kE / 128,   kM / 128), 256, GEMM_SMEM>>>(
        xh, wqh,  nullptr, qh,  QSCALE, kE,   kE, 1);
    gemm_f16<<<dim3(kKVN / 128, kM / 128), 256, GEMM_SMEM>>>(
        xh, wkvh, nullptr, kvh, 1.0f,   kKVN, kE, 1);

    // Attention (LPT order, double-buffered K/V, trans-LDSM V)
    attn_kernel<<<dim3(kT / 64, kB * kHQ / 2), 256, ATTN_SMEM>>>(qh, kvh, aoh);

    // O-projection (fp32 out)
    gemm_f16<<<dim3(kE / 128,   kM / 128), 256, GEMM_SMEM>>>(
        aoh, woh, out, nullptr, 1.0f, kE, kE, 0);
}

// round 14
// speedup vs baseline: 1.1624x; 1.1624x over previous
#include <cuda_runtime.h>
#include <cuda_fp16.h>
#include <math.h>
#include <stdint.h>

// Problem constants
#define kE   2048
#define kHQ  32
#define kHKV 8
#define kHD  64
#define kB   2
#define kT   2048
#define kM   (kB * kT)          // 4096 rows (B*T)
#define kKVN (2 * kHKV * kHD)   // 1024

#define QSCALE 0.1803368801111204f   // 0.125 * log2(e)

// ---------------------------------------------------------------------------
// Device-global scratch
// ---------------------------------------------------------------------------
__device__ __half g_qh[kM * kE];     // q projection, fp16, pre-scaled by QSCALE
__device__ __half g_kvh[kM * kKVN];  // kv projection fp16: k [0,512), v [512,1024)
__device__ __half g_xh[kM * kE];
__device__ __half g_wqh[kE * kE];
__device__ __half g_wkvh[kKVN * kE];
__device__ __half g_woh[kE * kE];
__device__ __half g_aoh[kM * kE];    // attention out, fp16

// ---------------------------------------------------------------------------
// Helpers
// ---------------------------------------------------------------------------
__device__ __forceinline__ uint32_t smem_u32(const void* p) {
    uint32_t a;
    asm("{ .reg .u64 t; cvta.to.shared.u64 t, %1; cvt.u32.u64 %0, t; }"
        : "=r"(a) : "l"(p));
    return a;
}

__device__ __forceinline__ void cp16(uint32_t saddr, const void* g) {
    asm volatile("cp.async.cg.shared.global [%0], [%1], 16;"
                 :: "r"(saddr), "l"(g) : "memory");
}
#define CP_COMMIT()  asm volatile("cp.async.commit_group;" ::: "memory")
#define CP_WAIT(n)   asm volatile("cp.async.wait_group %0;" :: "n"(n) : "memory")

#define LDSM4(r, addr)                                                        \
    asm volatile("ldmatrix.sync.aligned.m8n8.x4.shared.b16 {%0,%1,%2,%3}, [%4];" \
        : "=r"((r)[0]), "=r"((r)[1]), "=r"((r)[2]), "=r"((r)[3]) : "r"(addr))

#define LDSM4T(r, addr)                                                       \
    asm volatile("ldmatrix.sync.aligned.m8n8.x4.trans.shared.b16 {%0,%1,%2,%3}, [%4];" \
        : "=r"((r)[0]), "=r"((r)[1]), "=r"((r)[2]), "=r"((r)[3]) : "r"(addr))

// fp16 tensor op: D(16x8,f32) += A(16x16,f16) * B(16x8,f16)
__device__ __forceinline__ void mma_fp16(float* d, const uint32_t* a, const uint32_t* b) {
    asm volatile(
        "mma.sync.aligned.m16n8k16.row.col.f32.f16.f16.f32 "
        "{%0,%1,%2,%3},{%4,%5,%6,%7},{%8,%9},{%0,%1,%2,%3};\n"
        : "+f"(d[0]), "+f"(d[1]), "+f"(d[2]), "+f"(d[3])
        : "r"(a[0]), "r"(a[1]), "r"(a[2]), "r"(a[3]), "r"(b[0]), "r"(b[1]));
}

__device__ __forceinline__ uint32_t pack_h2(float a, float b) {
    __half2 h = __floats2half2_rn(a, b);
    return *reinterpret_cast<uint32_t*>(&h);
}

__device__ __forceinline__ float ex2(float x) {
    float r;
    asm("ex2.approx.ftz.f32 %0, %1;" : "=f"(r) : "f"(x));
    return r;
}

// ---------------------------------------------------------------------------
// Fused fp32 -> fp16 cast of x, Wq, Wkv, Wo (one launch)
// ---------------------------------------------------------------------------
#define C1 2097152              // x       float4 count
#define C2 (C1 + 1048576)       // + Wq
#define C3 (C2 + 524288)        // + Wkv
#define C4 (C3 + 1048576)       // + Wo

__global__ __launch_bounds__(256) void cast_all(
        const float* __restrict__ x,  const float* __restrict__ wq,
        const float* __restrict__ wkv, const float* __restrict__ wo,
        __half* __restrict__ xh, __half* __restrict__ wqh,
        __half* __restrict__ wkvh, __half* __restrict__ woh) {
    int i = blockIdx.x * 256 + threadIdx.x;
    if (i >= C4) return;
    const float* src; __half* dst; int off;
    if (i < C1)      { src = x;   dst = xh;   off = i; }
    else if (i < C2) { src = wq;  dst = wqh;  off = i - C1; }
    else if (i < C3) { src = wkv; dst = wkvh; off = i - C2; }
    else             { src = wo;  dst = woh;  off = i - C3; }
    float4 v = ((const float4*)src)[off];
    uint32_t* hp = (uint32_t*)dst;
    hp[2*off]   = pack_h2(v.x, v.y);
    hp[2*off+1] = pack_h2(v.z, v.w);
}

// ---------------------------------------------------------------------------
// GEMM: C[M,N] = scale * A[M,K] * W[N,K]^T, plain fp16 (R12 proven version).
// CTA 128x128, K-tile 32, 8 warps, 2-stage cp.async (CP_WAIT(1) depth),
// row stride 80B (20 words == 4 mod 32): conflict-free LDSM.
// ---------------------------------------------------------------------------
#define SPLANE_W 2560                       // 128 * 20 u32 words
#define SPLANE_B (SPLANE_W * 4)             // 10240 bytes
#define STAGE_B  (2 * SPLANE_B)             // A, W
#define GEMM_SMEM (2 * STAGE_B)             // 40960 bytes

__global__ __launch_bounds__(256) void gemm_f16(
        const __half* __restrict__ Ah, const __half* __restrict__ Whi,
        float* __restrict__ Cf, __half* __restrict__ Ch,
        float scale, int N, int K, int half_out) {
    extern __shared__ char smem[];
    const uint32_t sbase = smem_u32(smem);

    const int tid  = threadIdx.x;
    const int lane = tid & 31;
    const int wid  = tid >> 5;
    const int wm   = wid >> 1;        // 0..3
    const int wn   = wid & 1;         // 0..1
    const int m0   = blockIdx.y * 128;
    const int n0   = blockIdx.x * 128;

    float acc[2][8][4];
#pragma unroll
    for (int i = 0; i < 2; i++)
#pragma unroll
        for (int j = 0; j < 8; j++)
#pragma unroll
            for (int k = 0; k < 4; k++) acc[i][j][k] = 0.f;

    const size_t gs = (size_t)K * 2;  // bytes per global row
    const int crow  = tid >> 1;       // 0..127
    const int cbo   = (tid & 1) << 5; // 0 or 32 bytes

    const char* pA = (const char*)Ah;
    const char* pW = (const char*)Whi;

    const int NKT = K >> 5;

    auto copy_tile = [&](int s, int kt) {
        const uint32_t st = sbase + s * STAGE_B + crow * 80 + cbo;
        const size_t goA = (size_t)(m0 + crow) * gs + (size_t)kt * 64 + cbo;
        const size_t goW = (size_t)(n0 + crow) * gs + (size_t)kt * 64 + cbo;
        cp16(st,                 pA + goA);
        cp16(st + 16,            pA + goA + 16);
        cp16(st + SPLANE_B,      pW + goW);
        cp16(st + SPLANE_B + 16, pW + goW + 16);
    };

    copy_tile(0, 0);
    CP_COMMIT();

    // ldmatrix lane-address components
    const int lr8 = lane & 7;
    const int r8  = (lane >> 3) & 1;
    const int c4  = (lane >> 4) & 1;
    const uint32_t aoff0 = (uint32_t)((wm * 32 + lr8 + 8 * r8) * 80 + c4 * 16);
    const uint32_t aoff1 = aoff0 + 16 * 80;
    uint32_t boff[4];
#pragma unroll
    for (int np = 0; np < 4; np++)
        boff[np] = (uint32_t)((wn * 64 + np * 16 + lr8 + 8 * r8) * 80 + c4 * 16);

    const int rq = lane >> 2;
    const int wc = lane & 3;

    for (int kt = 0; kt < NKT; kt++) {
        if (kt + 1 < NKT) {
            copy_tile((kt + 1) & 1, kt + 1);
            CP_COMMIT();
            CP_WAIT(1);
        } else {
            CP_WAIT(0);
        }
        __syncthreads();

        const uint32_t stA = sbase + (kt & 1) * STAGE_B;
        const uint32_t stW = stA + SPLANE_B;

#pragma unroll
        for (int ks = 0; ks < 2; ks++) {
            const uint32_t ko = ks * 32;
            uint32_t ah[2][4];
            LDSM4(ah[0], stA + aoff0 + ko);
            LDSM4(ah[1], stA + aoff1 + ko);
            uint32_t bh[4][4];
#pragma unroll
            for (int np = 0; np < 4; np++)
                LDSM4(bh[np], stW + boff[np] + ko);
#pragma unroll
            for (int nt = 0; nt < 8; nt++) {
                const int np = nt >> 1, g = nt & 1;
                uint32_t bhf[2] = {bh[np][g], bh[np][2 + g]};
                mma_fp16(acc[0][nt], ah[0], bhf);
                mma_fp16(acc[1][nt], ah[1], bhf);
            }
        }
        __syncthreads();
    }

    if (half_out) {
#pragma unroll
        for (int mt = 0; mt < 2; mt++) {
            const int r = m0 + wm * 32 + mt * 16 + rq;
#pragma unroll
            for (int nt = 0; nt < 8; nt++) {
                const int c = n0 + wn * 64 + nt * 8 + (wc << 1);
                *(uint32_t*)&Ch[(size_t)r * N + c] =
                    pack_h2(acc[mt][nt][0] * scale, acc[mt][nt][1] * scale);
                *(uint32_t*)&Ch[(size_t)(r + 8) * N + c] =
                    pack_h2(acc[mt][nt][2] * scale, acc[mt][nt][3] * scale);
            }
        }
    } else {
#pragma unroll
        for (int mt = 0; mt < 2; mt++) {
            const int r = m0 + wm * 32 + mt * 16 + rq;
#pragma unroll
            for (int nt = 0; nt < 8; nt++) {
                const int c = n0 + wn * 64 + nt * 8 + (wc << 1);
                *(float2*)&Cf[(size_t)r * N + c]       = make_float2(acc[mt][nt][0], acc[mt][nt][1]);
                *(float2*)&Cf[(size_t)(r + 8) * N + c] = make_float2(acc[mt][nt][2], acc[mt][nt][3]);
            }
        }
    }
}

// ---------------------------------------------------------------------------
// Flash attention (causal, GQA), fp16 m16n8k16 (R13 proven version, 141 us).
// - cp.async double-buffered K/V, one barrier per kv-tile
// - V in natural [t][d] layout, B-fragments via ldmatrix.x4.trans
// - P stays in registers (C-frag == A-frag identity)
// - 2 query heads per CTA share the K/V stream; LPT launch order
// ---------------------------------------------------------------------------
#define AQ_OFF 0                         // Qs: 2 heads * 64 * 144 = 18432
#define AK_OFF 18432                     // K stages: 2 * 9216
#define AV_OFF 36864                     // V stages: 2 * 9216
#define ATTN_SMEM 55296

__global__ __launch_bounds__(256) void attn_kernel(
        const __half* __restrict__ qh, const __half* __restrict__ kvh,
        __half* __restrict__ aoh) {
    extern __shared__ char smc[];
    const uint32_t sb = smem_u32(smc);

    const int tid  = threadIdx.x;
    const int lane = tid & 31;
    const int w    = tid >> 5;          // 0..7
    const int wg   = w >> 2;            // head sub-index 0/1
    const int wl   = w & 3;             // warp within head
    const int qb   = gridDim.x - 1 - blockIdx.x;   // LPT: heavy blocks first
    const int pidx = blockIdx.y;        // (b, head-pair)
    const int b    = pidx >> 4;
    const int hp   = pidx & 15;
    const int hq   = hp * 2 + wg;
    const int hkv  = hp >> 1;

    const uint32_t qsu = sb + AQ_OFF + wg * 9216;

    // ---- Load both heads' Q tiles: pure 16B copies (fp16, pre-scaled)
    {
        const int half  = tid >> 7;               // 0/1 -> head
        const int hrow  = (tid & 127) >> 3;       // 0..15
        const int hcol  = (tid & 7) * 8;          // halves, 0..56
        const int hqh   = hp * 2 + half;
        char* Qdst = smc + AQ_OFF + half * 9216;
#pragma unroll
        for (int p = 0; p < 4; p++) {
            int row = p * 16 + hrow;
            const uint4 v = *(const uint4*)
                &qh[((size_t)(b * kT + qb * 64 + row)) * kE + hqh * kHD + hcol];
            *(uint4*)(Qdst + row * 144 + hcol * 2) = v;
        }
    }

    // K/V fill via cp.async: thread -> (row = tid>>2, 32B segment = tid&3)
    const int frow = tid >> 2;              // 0..63
    const int fsegh = (tid & 3) * 16;       // halves offset within row
    auto fill_kv = [&](int s, int j) {
        const __half* kg = kvh + ((size_t)(b * kT + j * 64 + frow)) * kKVN
                               + hkv * kHD + fsegh;
        const uint32_t stk = sb + AK_OFF + s * 9216 + frow * 144 + fsegh * 2;
        const uint32_t stv = sb + AV_OFF + s * 9216 + frow * 144 + fsegh * 2;
        cp16(stk,      kg);
        cp16(stk + 16, kg + 8);
        cp16(stv,      kg + 512);
        cp16(stv + 16, kg + 520);
    };

    float mrow0 = -INFINITY, mrow1 = -INFINITY;
    float lrow0 = 0.f, lrow1 = 0.f;
    float o[8][4];
#pragma unroll
    for (int nt = 0; nt < 8; nt++)
#pragma unroll
        for (int i = 0; i < 4; i++) o[nt][i] = 0.f;

    const int rloc = wl * 16 + (lane >> 2);   // warp's rows rloc, rloc+8 (0..63)

    // ldmatrix lane addresses
    const int lr8 = lane & 7;
    const int r8  = (lane >> 3) & 1;
    const int c4  = (lane >> 4) & 1;
    const uint32_t aoffQ = (uint32_t)((wl * 16 + lr8 + 8 * r8) * 144 + c4 * 16);
    uint32_t boffK[4];   // K: non-trans, [n][k]
#pragma unroll
    for (int np = 0; np < 4; np++)
        boffK[np] = (uint32_t)((np * 16 + lr8 + 8 * r8) * 144 + c4 * 16);
    uint32_t boffV[4];   // V: trans, [t][d]
#pragma unroll
    for (int np = 0; np < 4; np++)
        boffV[np] = (uint32_t)((lr8 + 8 * r8) * 144 + (np * 16 + 8 * c4) * 2);

    const int la = lane & 3;

    fill_kv(0, 0);
    CP_COMMIT();

    for (int j = 0; j <= qb; j++) {
        CP_WAIT(0);
        __syncthreads();                 // stage j&1 ready; other stage free
        if (j < qb) {
            fill_kv((j + 1) & 1, j + 1); // overlaps compute below
            CP_COMMIT();
        }

        const uint32_t ksu = sb + AK_OFF + (j & 1) * 9216;
        const uint32_t vsu = sb + AV_OFF + (j & 1) * 9216;

        // S = Q * K^T  (fp16 m16n8k16, 4 k-steps)
        float s[8][4];
#pragma unroll
        for (int nt = 0; nt < 8; nt++) { s[nt][0] = s[nt][1] = s[nt][2] = s[nt][3] = 0.f; }

#pragma unroll
        for (int ks = 0; ks < 4; ks++) {
            const uint32_t ko = ks * 32;
            uint32_t a[4];
            LDSM4(a, qsu + aoffQ + ko);
#pragma unroll
            for (int np = 0; np < 4; np++) {
                uint32_t kb[4];
                LDSM4(kb, ksu + boffK[np] + ko);
#pragma unroll
                for (int g = 0; g < 2; g++) {
                    uint32_t bb[2] = {kb[g], kb[2 + g]};
                    mma_fp16(s[2 * np + g], a, bb);
                }
            }
        }

        // Causal mask on the diagonal block
        if (j == qb) {
#pragma unroll
            for (int nt = 0; nt < 8; nt++) {
                int c0 = nt * 8 + (la << 1);
                if (c0     > rloc)     s[nt][0] = -INFINITY;
                if (c0 + 1 > rloc)     s[nt][1] = -INFINITY;
                if (c0     > rloc + 8) s[nt][2] = -INFINITY;
                if (c0 + 1 > rloc + 8) s[nt][3] = -INFINITY;
            }
        }

        // Online softmax (exp2 domain)
        float mx0 = -INFINITY, mx1 = -INFINITY;
#pragma unroll
        for (int nt = 0; nt < 8; nt++) {
            mx0 = fmaxf(mx0, fmaxf(s[nt][0], s[nt][1]));
            mx1 = fmaxf(mx1, fmaxf(s[nt][2], s[nt][3]));
        }
        mx0 = fmaxf(mx0, __shfl_xor_sync(0xffffffffu, mx0, 1));
        mx0 = fmaxf(mx0, __shfl_xor_sync(0xffffffffu, mx0, 2));
        mx1 = fmaxf(mx1, __shfl_xor_sync(0xffffffffu, mx1, 1));
        mx1 = fmaxf(mx1, __shfl_xor_sync(0xffffffffu, mx1, 2));

        float mnew0 = fmaxf(mrow0, mx0);
        float mnew1 = fmaxf(mrow1, mx1);
        float alpha0 = ex2(mrow0 - mnew0);
        float alpha1 = ex2(mrow1 - mnew1);
        mrow0 = mnew0; mrow1 = mnew1;

        float sum0 = 0.f, sum1 = 0.f;
#pragma unroll
        for (int nt = 0; nt < 8; nt++) {
            s[nt][0] = ex2(s[nt][0] - mnew0); sum0 += s[nt][0];
            s[nt][1] = ex2(s[nt][1] - mnew0); sum0 += s[nt][1];
            s[nt][2] = ex2(s[nt][2] - mnew1); sum1 += s[nt][2];
            s[nt][3] = ex2(s[nt][3] - mnew1); sum1 += s[nt][3];
        }
        sum0 += __shfl_xor_sync(0xffffffffu, sum0, 1);
        sum0 += __shfl_xor_sync(0xffffffffu, sum0, 2);
        sum1 += __shfl_xor_sync(0xffffffffu, sum1, 1);
        sum1 += __shfl_xor_sync(0xffffffffu, sum1, 2);

        lrow0 = lrow0 * alpha0 + sum0;
        lrow1 = lrow1 * alpha1 + sum1;

#pragma unroll
        for (int nt = 0; nt < 8; nt++) {
            o[nt][0] *= alpha0; o[nt][1] *= alpha0;
            o[nt][2] *= alpha1; o[nt][3] *= alpha1;
        }

        // O += P * V — P packed from S registers; V B-frags via ldmatrix.trans
#pragma unroll
        for (int ks = 0; ks < 4; ks++) {
            uint32_t a[4];
            a[0] = pack_h2(s[2*ks][0],   s[2*ks][1]);
            a[1] = pack_h2(s[2*ks][2],   s[2*ks][3]);
            a[2] = pack_h2(s[2*ks+1][0], s[2*ks+1][1]);
            a[3] = pack_h2(s[2*ks+1][2], s[2*ks+1][3]);
            const uint32_t vk = vsu + ks * 16 * 144;
#pragma unroll
            for (int np = 0; np < 4; np++) {
                uint32_t vb[4];
                LDSM4T(vb, vk + boffV[np]);
                mma_fp16(o[2 * np],     a, vb);       // n-block np*16..+7
                mma_fp16(o[2 * np + 1], a, vb + 2);   // n-block np*16+8..+15
            }
        }
        // no trailing barrier: top-of-loop barrier guards stage recycling
    }

    // Normalize and emit fp16 plane for the O-projection
    float inv0 = 1.f / lrow0;
    float inv1 = 1.f / lrow1;
    size_t r0 = (size_t)(b * kT + qb * 64 + rloc) * kE + hq * kHD;
    size_t r1 = (size_t)(b * kT + qb * 64 + rloc + 8) * kE + hq * kHD;
#pragma unroll
    for (int nt = 0; nt < 8; nt++) {
        int c = nt * 8 + (la << 1);
        *(uint32_t*)&aoh[r0 + c] = pack_h2(o[nt][0] * inv0, o[nt][1] * inv0);
        *(uint32_t*)&aoh[r1 + c] = pack_h2(o[nt][2] * inv1, o[nt][3] * inv1);
    }
}

// ---------------------------------------------------------------------------
// Launch
// ---------------------------------------------------------------------------
extern "C" void kernel_launch(void* const* d_in, const int* in_sizes, int n_in,
                              void* d_out, int out_size) {
    (void)in_sizes; (void)n_in; (void)out_size;
    const float* x   = (const float*)d_in[0];
    const float* Wq  = (const float*)d_in[1];
    const float* Wkv = (const float*)d_in[2];
    const float* Wo  = (const float*)d_in[3];
    float* out = (float*)d_out;

    __half *qh, *kvh, *xh, *wqh, *wkvh, *woh, *aoh;
    cudaGetSymbolAddress((void**)&qh,   g_qh);
    cudaGetSymbolAddress((void**)&kvh,  g_kvh);
    cudaGetSymbolAddress((void**)&xh,   g_xh);
    cudaGetSymbolAddress((void**)&wqh,  g_wqh);
    cudaGetSymbolAddress((void**)&wkvh, g_wkvh);
    cudaGetSymbolAddress((void**)&woh,  g_woh);
    cudaGetSymbolAddress((void**)&aoh,  g_aoh);

    cudaFuncSetAttribute(gemm_f16,
                         cudaFuncAttributeMaxDynamicSharedMemorySize, GEMM_SMEM);
    cudaFuncSetAttribute(attn_kernel,
                         cudaFuncAttributeMaxDynamicSharedMemorySize, ATTN_SMEM);

    // One fused cast launch (x, Wq, Wkv, Wo -> fp16)
    cast_all<<<(C4 + 255) / 256, 256>>>(x, Wq, Wkv, Wo, xh, wqh, wkvh, woh);

    // Projections: plain fp16 GEMMs; q/kv emit fp16 (q pre-scaled for exp2)
    gemm_f16<<<dim3(kE / 128,   kM / 128), 256, GEMM_SMEM>>>(
        xh, wqh,  nullptr, qh,  QSCALE, kE,   kE, 1);
    gemm_f16<<<dim3(kKVN / 128, kM / 128), 256, GEMM_SMEM>>>(
        xh, wkvh, nullptr, kvh, 1.0f,   kKVN, kE, 1);

    // Attention (LPT order, double-buffered K/V, trans-LDSM V)
    attn_kernel<<<dim3(kT / 64, kB * kHQ / 2), 256, ATTN_SMEM>>>(qh, kvh, aoh);

    // O-projection (fp32 out)
    gemm_f16<<<dim3(kE / 128,   kM / 128), 256, GEMM_SMEM>>>(
        aoh, woh, out, nullptr, 1.0f, kE, kE, 0);
}

// round 15
// speedup vs baseline: 1.1725x; 1.0087x over previous
#include <cuda_runtime.h>
#include <cuda_fp16.h>
#include <math.h>
#include <stdint.h>

// Problem constants
#define kE   2048
#define kHQ  32
#define kHKV 8
#define kHD  64
#define kB   2
#define kT   2048
#define kM   (kB * kT)          // 4096 rows (B*T)
#define kKVN (2 * kHKV * kHD)   // 1024
#define kNF  (kE + kKVN)        // 3072 fused q+kv output cols

#define QSCALE 0.1803368801111204f   // 0.125 * log2(e)

// ---------------------------------------------------------------------------
// Device-global scratch
// ---------------------------------------------------------------------------
__device__ __half g_qh[kM * kE];     // q projection, fp16, pre-scaled by QSCALE
__device__ __half g_kvh[kM * kKVN];  // kv projection fp16: k [0,512), v [512,1024)
__device__ __half g_xh[kM * kE];
__device__ __half g_wch[kNF * kE];   // fused weights: Wq rows 0..2047, Wkv rows 2048..3071
__device__ __half g_woh[kE * kE];
__device__ __half g_aoh[kM * kE];    // attention out, fp16

// ---------------------------------------------------------------------------
// Helpers
// ---------------------------------------------------------------------------
__device__ __forceinline__ uint32_t smem_u32(const void* p) {
    uint32_t a;
    asm("{ .reg .u64 t; cvta.to.shared.u64 t, %1; cvt.u32.u64 %0, t; }"
        : "=r"(a) : "l"(p));
    return a;
}

__device__ __forceinline__ void cp16(uint32_t saddr, const void* g) {
    asm volatile("cp.async.cg.shared.global [%0], [%1], 16;"
                 :: "r"(saddr), "l"(g) : "memory");
}
#define CP_COMMIT()  asm volatile("cp.async.commit_group;" ::: "memory")
#define CP_WAIT(n)   asm volatile("cp.async.wait_group %0;" :: "n"(n) : "memory")

#define LDSM4(r, addr)                                                        \
    asm volatile("ldmatrix.sync.aligned.m8n8.x4.shared.b16 {%0,%1,%2,%3}, [%4];" \
        : "=r"((r)[0]), "=r"((r)[1]), "=r"((r)[2]), "=r"((r)[3]) : "r"(addr))

#define LDSM4T(r, addr)                                                       \
    asm volatile("ldmatrix.sync.aligned.m8n8.x4.trans.shared.b16 {%0,%1,%2,%3}, [%4];" \
        : "=r"((r)[0]), "=r"((r)[1]), "=r"((r)[2]), "=r"((r)[3]) : "r"(addr))

// fp16 tensor op: D(16x8,f32) += A(16x16,f16) * B(16x8,f16)
__device__ __forceinline__ void mma_fp16(float* d, const uint32_t* a, const uint32_t* b) {
    asm volatile(
        "mma.sync.aligned.m16n8k16.row.col.f32.f16.f16.f32 "
        "{%0,%1,%2,%3},{%4,%5,%6,%7},{%8,%9},{%0,%1,%2,%3};\n"
        : "+f"(d[0]), "+f"(d[1]), "+f"(d[2]), "+f"(d[3])
        : "r"(a[0]), "r"(a[1]), "r"(a[2]), "r"(a[3]), "r"(b[0]), "r"(b[1]));
}

__device__ __forceinline__ uint32_t pack_h2(float a, float b) {
    __half2 h = __floats2half2_rn(a, b);
    return *reinterpret_cast<uint32_t*>(&h);
}

__device__ __forceinline__ float ex2(float x) {
    float r;
    asm("ex2.approx.ftz.f32 %0, %1;" : "=f"(r) : "f"(x));
    return r;
}

// ---------------------------------------------------------------------------
// Fused fp32 -> fp16 cast: x -> xh; Wq,Wkv -> combined wch; Wo -> woh
// ---------------------------------------------------------------------------
#define C1 2097152              // x       float4 count
#define C2 (C1 + 1048576)       // + Wq
#define C3 (C2 + 524288)        // + Wkv
#define C4 (C3 + 1048576)       // + Wo

__global__ __launch_bounds__(256) void cast_all(
        const float* __restrict__ x,  const float* __restrict__ wq,
        const float* __restrict__ wkv, const float* __restrict__ wo,
        __half* __restrict__ xh, __half* __restrict__ wch,
        __half* __restrict__ woh) {
    int i = blockIdx.x * 256 + threadIdx.x;
    if (i >= C4) return;
    const float* src; __half* dst; int off;
    if (i < C1)      { src = x;   dst = xh;                    off = i; }
    else if (i < C2) { src = wq;  dst = wch;                   off = i - C1; }
    else if (i < C3) { src = wkv; dst = wch + (size_t)kE * kE / 2; off = i - C2; }  // half4 offset
    else             { src = wo;  dst = woh;                   off = i - C3; }
    // note: wch+kE*kE elements == float4 index offset kE*kE/4; dst is __half*,
    // and we index by float4 slot below, so adjust: use element math directly.
    float4 v = ((const float4*)src)[off];
    uint32_t* hp;
    if (i >= C2 && i < C3) {
        hp = (uint32_t*)(wch + (size_t)kE * kE) + 2 * (size_t)off;
    } else {
        hp = (uint32_t*)dst + 2 * (size_t)off;
    }
    hp[0] = pack_h2(v.x, v.y);
    hp[1] = pack_h2(v.z, v.w);
}

// ---------------------------------------------------------------------------
// GEMM: C = A[M,K] * W[N,K]^T, plain fp16 (R12/R14 proven inner loop).
// mode 1 (fused q/kv): n0<2048 -> qh (scale QSCALE, stride kE),
//                      else    -> kvh (scale 1, stride kKVN)
// mode 0: fp32 out, stride kE.
// ---------------------------------------------------------------------------
#define SPLANE_W 2560                       // 128 * 20 u32 words
#define SPLANE_B (SPLANE_W * 4)             // 10240 bytes
#define STAGE_B  (2 * SPLANE_B)             // A, W
#define GEMM_SMEM (2 * STAGE_B)             // 40960 bytes

__global__ __launch_bounds__(256) void gemm_f16(
        const __half* __restrict__ Ah, const __half* __restrict__ Whi,
        float* __restrict__ Cf, __half* __restrict__ Chq, __half* __restrict__ Chkv,
        int K, int half_out) {
    extern __shared__ char smem[];
    const uint32_t sbase = smem_u32(smem);

    const int tid  = threadIdx.x;
    const int lane = tid & 31;
    const int wid  = tid >> 5;
    const int wm   = wid >> 1;        // 0..3
    const int wn   = wid & 1;         // 0..1
    const int m0   = blockIdx.y * 128;
    const int n0   = blockIdx.x * 128;

    float acc[2][8][4];
#pragma unroll
    for (int i = 0; i < 2; i++)
#pragma unroll
        for (int j = 0; j < 8; j++)
#pragma unroll
            for (int k = 0; k < 4; k++) acc[i][j][k] = 0.f;

    const size_t gs = (size_t)K * 2;  // bytes per global row
    const int crow  = tid >> 1;       // 0..127
    const int cbo   = (tid & 1) << 5; // 0 or 32 bytes

    const char* pA = (const char*)Ah;
    const char* pW = (const char*)Whi;

    const int NKT = K >> 5;

    auto copy_tile = [&](int s, int kt) {
        const uint32_t st = sbase + s * STAGE_B + crow * 80 + cbo;
        const size_t goA = (size_t)(m0 + crow) * gs + (size_t)kt * 64 + cbo;
        const size_t goW = (size_t)(n0 + crow) * gs + (size_t)kt * 64 + cbo;
        cp16(st,                 pA + goA);
        cp16(st + 16,            pA + goA + 16);
        cp16(st + SPLANE_B,      pW + goW);
        cp16(st + SPLANE_B + 16, pW + goW + 16);
    };

    copy_tile(0, 0);
    CP_COMMIT();

    // ldmatrix lane-address components
    const int lr8 = lane & 7;
    const int r8  = (lane >> 3) & 1;
    const int c4  = (lane >> 4) & 1;
    const uint32_t aoff0 = (uint32_t)((wm * 32 + lr8 + 8 * r8) * 80 + c4 * 16);
    const uint32_t aoff1 = aoff0 + 16 * 80;
    uint32_t boff[4];
#pragma unroll
    for (int np = 0; np < 4; np++)
        boff[np] = (uint32_t)((wn * 64 + np * 16 + lr8 + 8 * r8) * 80 + c4 * 16);

    const int rq = lane >> 2;
    const int wc = lane & 3;

    for (int kt = 0; kt < NKT; kt++) {
        if (kt + 1 < NKT) {
            copy_tile((kt + 1) & 1, kt + 1);
            CP_COMMIT();
            CP_WAIT(1);
        } else {
            CP_WAIT(0);
        }
        __syncthreads();

        const uint32_t stA = sbase + (kt & 1) * STAGE_B;
        const uint32_t stW = stA + SPLANE_B;

#pragma unroll
        for (int ks = 0; ks < 2; ks++) {
            const uint32_t ko = ks * 32;
            uint32_t ah[2][4];
            LDSM4(ah[0], stA + aoff0 + ko);
            LDSM4(ah[1], stA + aoff1 + ko);
            uint32_t bh[4][4];
#pragma unroll
            for (int np = 0; np < 4; np++)
                LDSM4(bh[np], stW + boff[np] + ko);
#pragma unroll
            for (int nt = 0; nt < 8; nt++) {
                const int np = nt >> 1, g = nt & 1;
                uint32_t bhf[2] = {bh[np][g], bh[np][2 + g]};
                mma_fp16(acc[0][nt], ah[0], bhf);
                mma_fp16(acc[1][nt], ah[1], bhf);
            }
        }
        __syncthreads();
    }

    if (half_out) {
        // fused q/kv epilogue: whole CTA is on one side of the 2048 boundary
        __half* dst;
        int cbase, stride;
        float sc;
        if (n0 < kE) { dst = Chq;  cbase = n0;       stride = kE;   sc = QSCALE; }
        else         { dst = Chkv; cbase = n0 - kE;  stride = kKVN; sc = 1.0f;   }
#pragma unroll
        for (int mt = 0; mt < 2; mt++) {
            const int r = m0 + wm * 32 + mt * 16 + rq;
#pragma unroll
            for (int nt = 0; nt < 8; nt++) {
                const int c = cbase + wn * 64 + nt * 8 + (wc << 1);
                *(uint32_t*)&dst[(size_t)r * stride + c] =
                    pack_h2(acc[mt][nt][0] * sc, acc[mt][nt][1] * sc);
                *(uint32_t*)&dst[(size_t)(r + 8) * stride + c] =
                    pack_h2(acc[mt][nt][2] * sc, acc[mt][nt][3] * sc);
            }
        }
    } else {
#pragma unroll
        for (int mt = 0; mt < 2; mt++) {
            const int r = m0 + wm * 32 + mt * 16 + rq;
#pragma unroll
            for (int nt = 0; nt < 8; nt++) {
                const int c = n0 + wn * 64 + nt * 8 + (wc << 1);
                *(float2*)&Cf[(size_t)r * kE + c]       = make_float2(acc[mt][nt][0], acc[mt][nt][1]);
                *(float2*)&Cf[(size_t)(r + 8) * kE + c] = make_float2(acc[mt][nt][2], acc[mt][nt][3]);
            }
        }
    }
}

// ---------------------------------------------------------------------------
// Flash attention (causal, GQA), fp16 m16n8k16.
// R13/R14 proven body + Q fragments hoisted out of the j-loop.
// ---------------------------------------------------------------------------
#define AQ_OFF 0                         // Qs: 2 heads * 64 * 144 = 18432
#define AK_OFF 18432                     // K stages: 2 * 9216
#define AV_OFF 36864                     // V stages: 2 * 9216
#define ATTN_SMEM 55296

__global__ __launch_bounds__(256) void attn_kernel(
        const __half* __restrict__ qh, const __half* __restrict__ kvh,
        __half* __restrict__ aoh) {
    extern __shared__ char smc[];
    const uint32_t sb = smem_u32(smc);

    const int tid  = threadIdx.x;
    const int lane = tid & 31;
    const int w    = tid >> 5;          // 0..7
    const int wg   = w >> 2;            // head sub-index 0/1
    const int wl   = w & 3;             // warp within head
    const int qb   = gridDim.x - 1 - blockIdx.x;   // LPT: heavy blocks first
    const int pidx = blockIdx.y;        // (b, head-pair)
    const int b    = pidx >> 4;
    const int hp   = pidx & 15;
    const int hq   = hp * 2 + wg;
    const int hkv  = hp >> 1;

    const uint32_t qsu = sb + AQ_OFF + wg * 9216;

    // ---- Load both heads' Q tiles: pure 16B copies (fp16, pre-scaled)
    {
        const int half  = tid >> 7;               // 0/1 -> head
        const int hrow  = (tid & 127) >> 3;       // 0..15
        const int hcol  = (tid & 7) * 8;          // halves, 0..56
        const int hqh   = hp * 2 + half;
        char* Qdst = smc + AQ_OFF + half * 9216;
#pragma unroll
        for (int p = 0; p < 4; p++) {
            int row = p * 16 + hrow;
            const uint4 v = *(const uint4*)
                &qh[((size_t)(b * kT + qb * 64 + row)) * kE + hqh * kHD + hcol];
            *(uint4*)(Qdst + row * 144 + hcol * 2) = v;
        }
    }

    // K/V fill via cp.async
    const int frow = tid >> 2;              // 0..63
    const int fsegh = (tid & 3) * 16;       // halves offset within row
    auto fill_kv = [&](int s, int j) {
        const __half* kg = kvh + ((size_t)(b * kT + j * 64 + frow)) * kKVN
                               + hkv * kHD + fsegh;
        const uint32_t stk = sb + AK_OFF + s * 9216 + frow * 144 + fsegh * 2;
        const uint32_t stv = sb + AV_OFF + s * 9216 + frow * 144 + fsegh * 2;
        cp16(stk,      kg);
        cp16(stk + 16, kg + 8);
        cp16(stv,      kg + 512);
        cp16(stv + 16, kg + 520);
    };

    float mrow0 = -INFINITY, mrow1 = -INFINITY;
    float lrow0 = 0.f, lrow1 = 0.f;
    float o[8][4];
#pragma unroll
    for (int nt = 0; nt < 8; nt++)
#pragma unroll
        for (int i = 0; i < 4; i++) o[nt][i] = 0.f;

    const int rloc = wl * 16 + (lane >> 2);   // warp's rows rloc, rloc+8 (0..63)

    // ldmatrix lane addresses
    const int lr8 = lane & 7;
    const int r8  = (lane >> 3) & 1;
    const int c4  = (lane >> 4) & 1;
    const uint32_t aoffQ = (uint32_t)((wl * 16 + lr8 + 8 * r8) * 144 + c4 * 16);
    uint32_t boffK[4];   // K: non-trans, [n][k]
#pragma unroll
    for (int np = 0; np < 4; np++)
        boffK[np] = (uint32_t)((np * 16 + lr8 + 8 * r8) * 144 + c4 * 16);
    uint32_t boffV[4];   // V: trans, [t][d]
#pragma unroll
    for (int np = 0; np < 4; np++)
        boffV[np] = (uint32_t)((lr8 + 8 * r8) * 144 + (np * 16 + 8 * c4) * 2);

    const int la = lane & 3;

    fill_kv(0, 0);
    CP_COMMIT();

    // Hoist Q fragments (loop-invariant): one barrier to make Q tile visible
    __syncthreads();
    uint32_t qa[4][4];
#pragma unroll
    for (int ks = 0; ks < 4; ks++)
        LDSM4(qa[ks], qsu + aoffQ + ks * 32);

    for (int j = 0; j <= qb; j++) {
        CP_WAIT(0);
        __syncthreads();                 // stage j&1 ready; other stage free
        if (j < qb) {
            fill_kv((j + 1) & 1, j + 1); // overlaps compute below
            CP_COMMIT();
        }

        const uint32_t ksu = sb + AK_OFF + (j & 1) * 9216;
        const uint32_t vsu = sb + AV_OFF + (j & 1) * 9216;

        // S = Q * K^T  (fp16 m16n8k16, 4 k-steps)
        float s[8][4];
#pragma unroll
        for (int nt = 0; nt < 8; nt++) { s[nt][0] = s[nt][1] = s[nt][2] = s[nt][3] = 0.f; }

#pragma unroll
        for (int ks = 0; ks < 4; ks++) {
            const uint32_t ko = ks * 32;
#pragma unroll
            for (int np = 0; np < 4; np++) {
                uint32_t kb[4];
                LDSM4(kb, ksu + boffK[np] + ko);
#pragma unroll
                for (int g = 0; g < 2; g++) {
                    uint32_t bb[2] = {kb[g], kb[2 + g]};
                    mma_fp16(s[2 * np + g], qa[ks], bb);
                }
            }
        }

        // Causal mask on the diagonal block
        if (j == qb) {
#pragma unroll
            for (int nt = 0; nt < 8; nt++) {
                int c0 = nt * 8 + (la << 1);
                if (c0     > rloc)     s[nt][0] = -INFINITY;
                if (c0 + 1 > rloc)     s[nt][1] = -INFINITY;
                if (c0     > rloc + 8) s[nt][2] = -INFINITY;
                if (c0 + 1 > rloc + 8) s[nt][3] = -INFINITY;
            }
        }

        // Online softmax (exp2 domain)
        float mx0 = -INFINITY, mx1 = -INFINITY;
#pragma unroll
        for (int nt = 0; nt < 8; nt++) {
            mx0 = fmaxf(mx0, fmaxf(s[nt][0], s[nt][1]));
            mx1 = fmaxf(mx1, fmaxf(s[nt][2], s[nt][3]));
        }
        mx0 = fmaxf(mx0, __shfl_xor_sync(0xffffffffu, mx0, 1));
        mx0 = fmaxf(mx0, __shfl_xor_sync(0xffffffffu, mx0, 2));
        mx1 = fmaxf(mx1, __shfl_xor_sync(0xffffffffu, mx1, 1));
        mx1 = fmaxf(mx1, __shfl_xor_sync(0xffffffffu, mx1, 2));

        float mnew0 = fmaxf(mrow0, mx0);
        float mnew1 = fmaxf(mrow1, mx1);
        float alpha0 = ex2(mrow0 - mnew0);
        float alpha1 = ex2(mrow1 - mnew1);
        mrow0 = mnew0; mrow1 = mnew1;

        float sum0 = 0.f, sum1 = 0.f;
#pragma unroll
        for (int nt = 0; nt < 8; nt++) {
            s[nt][0] = ex2(s[nt][0] - mnew0); sum0 += s[nt][0];
            s[nt][1] = ex2(s[nt][1] - mnew0); sum0 += s[nt][1];
            s[nt][2] = ex2(s[nt][2] - mnew1); sum1 += s[nt][2];
            s[nt][3] = ex2(s[nt][3] - mnew1); sum1 += s[nt][3];
        }
        sum0 += __shfl_xor_sync(0xffffffffu, sum0, 1);
        sum0 += __shfl_xor_sync(0xffffffffu, sum0, 2);
        sum1 += __shfl_xor_sync(0xffffffffu, sum1, 1);
        sum1 += __shfl_xor_sync(0xffffffffu, sum1, 2);

        lrow0 = lrow0 * alpha0 + sum0;
        lrow1 = lrow1 * alpha1 + sum1;

#pragma unroll
        for (int nt = 0; nt < 8; nt++) {
            o[nt][0] *= alpha0; o[nt][1] *= alpha0;
            o[nt][2] *= alpha1; o[nt][3] *= alpha1;
        }

        // O += P * V — P packed from S registers; V B-frags via ldmatrix.trans
#pragma unroll
        for (int ks = 0; ks < 4; ks++) {
            uint32_t a[4];
            a[0] = pack_h2(s[2*ks][0],   s[2*ks][1]);
            a[1] = pack_h2(s[2*ks][2],   s[2*ks][3]);
            a[2] = pack_h2(s[2*ks+1][0], s[2*ks+1][1]);
            a[3] = pack_h2(s[2*ks+1][2], s[2*ks+1][3]);
            const uint32_t vk = vsu + ks * 16 * 144;
#pragma unroll
            for (int np = 0; np < 4; np++) {
                uint32_t vb[4];
                LDSM4T(vb, vk + boffV[np]);
                mma_fp16(o[2 * np],     a, vb);       // n-block np*16..+7
                mma_fp16(o[2 * np + 1], a, vb + 2);   // n-block np*16+8..+15
            }
        }
        // no trailing barrier: top-of-loop barrier guards stage recycling
    }

    // Normalize and emit fp16 plane for the O-projection
    float inv0 = 1.f / lrow0;
    float inv1 = 1.f / lrow1;
    size_t r0 = (size_t)(b * kT + qb * 64 + rloc) * kE + hq * kHD;
    size_t r1 = (size_t)(b * kT + qb * 64 + rloc + 8) * kE + hq * kHD;
#pragma unroll
    for (int nt = 0; nt < 8; nt++) {
        int c = nt * 8 + (la << 1);
        *(uint32_t*)&aoh[r0 + c] = pack_h2(o[nt][0] * inv0, o[nt][1] * inv0);
        *(uint32_t*)&aoh[r1 + c] = pack_h2(o[nt][2] * inv1, o[nt][3] * inv1);
    }
}

// ---------------------------------------------------------------------------
// Launch
// ---------------------------------------------------------------------------
extern "C" void kernel_launch(void* const* d_in, const int* in_sizes, int n_in,
                              void* d_out, int out_size) {
    (void)in_sizes; (void)n_in; (void)out_size;
    const float* x   = (const float*)d_in[0];
    const float* Wq  = (const float*)d_in[1];
    const float* Wkv = (const float*)d_in[2];
    const float* Wo  = (const float*)d_in[3];
    float* out = (float*)d_out;

    __half *qh, *kvh, *xh, *wch, *woh, *aoh;
    cudaGetSymbolAddress((void**)&qh,  g_qh);
    cudaGetSymbolAddress((void**)&kvh, g_kvh);
    cudaGetSymbolAddress((void**)&xh,  g_xh);
    cudaGetSymbolAddress((void**)&wch, g_wch);
    cudaGetSymbolAddress((void**)&woh, g_woh);
    cudaGetSymbolAddress((void**)&aoh, g_aoh);

    cudaFuncSetAttribute(gemm_f16,
                         cudaFuncAttributeMaxDynamicSharedMemorySize, GEMM_SMEM);
    cudaFuncSetAttribute(attn_kernel,
                         cudaFuncAttributeMaxDynamicSharedMemorySize, ATTN_SMEM);

    // One fused cast launch (x -> xh; Wq+Wkv -> wch; Wo -> woh)
    cast_all<<<(C4 + 255) / 256, 256>>>(x, Wq, Wkv, Wo, xh, wch, woh);

    // Fused q+kv projection: one N=3072 GEMM, epilogue routes per side
    gemm_f16<<<dim3(kNF / 128, kM / 128), 256, GEMM_SMEM>>>(
        xh, wch, nullptr, qh, kvh, kE, 1);

    // Attention (LPT order, double-buffered K/V, hoisted Q frags)
    attn_kernel<<<dim3(kT / 64, kB * kHQ / 2), 256, ATTN_SMEM>>>(qh, kvh, aoh);

    // O-projection (fp32 out)
    gemm_f16<<<dim3(kE / 128, kM / 128), 256, GEMM_SMEM>>>(
        aoh, woh, out, nullptr, nullptr, kE, 0);
}

// round 16
// speedup vs baseline: 1.2237x; 1.0437x over previous
#include <cuda_runtime.h>
#include <cuda_fp16.h>
#include <math.h>
#include <stdint.h>

// Problem constants
#define kE   2048
#define kHQ  32
#define kHKV 8
#define kHD  64
#define kB   2
#define kT   2048
#define kM   (kB * kT)          // 4096 rows (B*T)
#define kKVN (2 * kHKV * kHD)   // 1024
#define kNF  (kE + kKVN)        // 3072 fused q+kv output cols

#define QSCALE 0.1803368801111204f   // 0.125 * log2(e)

// ---------------------------------------------------------------------------
// Device-global scratch
// ---------------------------------------------------------------------------
__device__ __half g_qh[kM * kE];     // q projection, fp16, pre-scaled by QSCALE
__device__ __half g_kvh[kM * kKVN];  // kv projection fp16: k [0,512), v [512,1024)
__device__ __half g_xh[kM * kE];
__device__ __half g_wch[kNF * kE];   // fused weights: Wq rows 0..2047, Wkv rows 2048..3071
__device__ __half g_woh[kE * kE];
__device__ __half g_aoh[kM * kE];    // attention out, fp16

// ---------------------------------------------------------------------------
// Helpers
// ---------------------------------------------------------------------------
__device__ __forceinline__ uint32_t smem_u32(const void* p) {
    uint32_t a;
    asm("{ .reg .u64 t; cvta.to.shared.u64 t, %1; cvt.u32.u64 %0, t; }"
        : "=r"(a) : "l"(p));
    return a;
}

__device__ __forceinline__ void cp16(uint32_t saddr, const void* g) {
    asm volatile("cp.async.cg.shared.global [%0], [%1], 16;"
                 :: "r"(saddr), "l"(g) : "memory");
}
#define CP_COMMIT()  asm volatile("cp.async.commit_group;" ::: "memory")
#define CP_WAIT(n)   asm volatile("cp.async.wait_group %0;" :: "n"(n) : "memory")

#define LDSM4(r, addr)                                                        \
    asm volatile("ldmatrix.sync.aligned.m8n8.x4.shared.b16 {%0,%1,%2,%3}, [%4];" \
        : "=r"((r)[0]), "=r"((r)[1]), "=r"((r)[2]), "=r"((r)[3]) : "r"(addr))

#define LDSM4T(r, addr)                                                       \
    asm volatile("ldmatrix.sync.aligned.m8n8.x4.trans.shared.b16 {%0,%1,%2,%3}, [%4];" \
        : "=r"((r)[0]), "=r"((r)[1]), "=r"((r)[2]), "=r"((r)[3]) : "r"(addr))

// fp16 tensor op: D(16x8,f32) += A(16x16,f16) * B(16x8,f16)
__device__ __forceinline__ void mma_fp16(float* d, const uint32_t* a, const uint32_t* b) {
    asm volatile(
        "mma.sync.aligned.m16n8k16.row.col.f32.f16.f16.f32 "
        "{%0,%1,%2,%3},{%4,%5,%6,%7},{%8,%9},{%0,%1,%2,%3};\n"
        : "+f"(d[0]), "+f"(d[1]), "+f"(d[2]), "+f"(d[3])
        : "r"(a[0]), "r"(a[1]), "r"(a[2]), "r"(a[3]), "r"(b[0]), "r"(b[1]));
}

__device__ __forceinline__ uint32_t pack_h2(float a, float b) {
    __half2 h = __floats2half2_rn(a, b);
    return *reinterpret_cast<uint32_t*>(&h);
}

__device__ __forceinline__ float ex2(float x) {
    float r;
    asm("ex2.approx.ftz.f32 %0, %1;" : "=f"(r) : "f"(x));
    return r;
}

// ---------------------------------------------------------------------------
// Fused fp32 -> fp16 cast: x -> xh; Wq,Wkv -> combined wch; Wo -> woh
// ---------------------------------------------------------------------------
#define C1 2097152              // x       float4 count
#define C2 (C1 + 1048576)       // + Wq
#define C3 (C2 + 524288)        // + Wkv
#define C4 (C3 + 1048576)       // + Wo

__global__ __launch_bounds__(256) void cast_all(
        const float* __restrict__ x,  const float* __restrict__ wq,
        const float* __restrict__ wkv, const float* __restrict__ wo,
        __half* __restrict__ xh, __half* __restrict__ wch,
        __half* __restrict__ woh) {
    int i = blockIdx.x * 256 + threadIdx.x;
    if (i >= C4) return;
    const float* src; __half* dst; int off;
    if (i < C1)      { src = x;   dst = xh;  off = i; }
    else if (i < C2) { src = wq;  dst = wch; off = i - C1; }
    else if (i < C3) { src = wkv; dst = wch; off = i - C2; }
    else             { src = wo;  dst = woh; off = i - C3; }
    float4 v = ((const float4*)src)[off];
    uint32_t* hp;
    if (i >= C2 && i < C3) {
        hp = (uint32_t*)(wch + (size_t)kE * kE) + 2 * (size_t)off;
    } else {
        hp = (uint32_t*)dst + 2 * (size_t)off;
    }
    hp[0] = pack_h2(v.x, v.y);
    hp[1] = pack_h2(v.z, v.w);
}

// ---------------------------------------------------------------------------
// GEMM: C = A[M,K] * W[N,K]^T, plain fp16.
// CTA 128x128, K-tile 32, 4 warps with 64x64 warp tiles (2x2 grid):
//   - B duplication 4x -> 2x (smem traffic/k-tile 64KB -> 48KB)
//   - 32 independent MMAs per LDSM group (4x ILP per warp)
// 2-stage cp.async (R12 staging pattern), row stride 80B (conflict-free LDSM).
// mode 1 (fused q/kv): n0<2048 -> qh (QSCALE, stride kE), else kvh (1, kKVN).
// mode 0: fp32 out, stride kE.
// ---------------------------------------------------------------------------
#define SPLANE_W 2560                       // 128 * 20 u32 words
#define SPLANE_B (SPLANE_W * 4)             // 10240 bytes
#define STAGE_B  (2 * SPLANE_B)             // A, W
#define GEMM_SMEM (2 * STAGE_B)             // 40960 bytes

__global__ __launch_bounds__(128) void gemm_f16(
        const __half* __restrict__ Ah, const __half* __restrict__ Whi,
        float* __restrict__ Cf, __half* __restrict__ Chq, __half* __restrict__ Chkv,
        int K, int half_out) {
    extern __shared__ char smem[];
    const uint32_t sbase = smem_u32(smem);

    const int tid  = threadIdx.x;
    const int lane = tid & 31;
    const int wid  = tid >> 5;        // 0..3
    const int wm   = wid >> 1;        // 0..1 (64 rows each)
    const int wn   = wid & 1;         // 0..1 (64 cols each)
    const int m0   = blockIdx.y * 128;
    const int n0   = blockIdx.x * 128;

    float acc[4][8][4];
#pragma unroll
    for (int i = 0; i < 4; i++)
#pragma unroll
        for (int j = 0; j < 8; j++)
#pragma unroll
            for (int k = 0; k < 4; k++) acc[i][j][k] = 0.f;

    const size_t gs = (size_t)K * 2;  // bytes per global row
    const int crow  = tid >> 1;       // 0..63
    const int cbo   = (tid & 1) << 5; // 0 or 32 bytes

    const char* pA = (const char*)Ah;
    const char* pW = (const char*)Whi;

    const int NKT = K >> 5;

    // R12-proven per-instruction staging pattern (16 rows x 2 chunks / warp)
    auto copy_tile = [&](int s, int kt) {
#pragma unroll
        for (int h = 0; h < 2; h++) {
            const int row = h * 64 + crow;
            const uint32_t st = sbase + s * STAGE_B + row * 80 + cbo;
            const size_t goA = (size_t)(m0 + row) * gs + (size_t)kt * 64 + cbo;
            const size_t goW = (size_t)(n0 + row) * gs + (size_t)kt * 64 + cbo;
            cp16(st,                 pA + goA);
            cp16(st + 16,            pA + goA + 16);
            cp16(st + SPLANE_B,      pW + goW);
            cp16(st + SPLANE_B + 16, pW + goW + 16);
        }
    };

    copy_tile(0, 0);
    CP_COMMIT();

    // ldmatrix lane-address components
    const int lr8 = lane & 7;
    const int r8  = (lane >> 3) & 1;
    const int c4  = (lane >> 4) & 1;
    uint32_t aoffm[4], boffn[4];
#pragma unroll
    for (int mt = 0; mt < 4; mt++)
        aoffm[mt] = (uint32_t)((wm * 64 + mt * 16 + lr8 + 8 * r8) * 80 + c4 * 16);
#pragma unroll
    for (int np = 0; np < 4; np++)
        boffn[np] = (uint32_t)((wn * 64 + np * 16 + lr8 + 8 * r8) * 80 + c4 * 16);

    const int rq = lane >> 2;
    const int wc = lane & 3;

    for (int kt = 0; kt < NKT; kt++) {
        if (kt + 1 < NKT) {
            copy_tile((kt + 1) & 1, kt + 1);
            CP_COMMIT();
            CP_WAIT(1);
        } else {
            CP_WAIT(0);
        }
        __syncthreads();

        const uint32_t stA = sbase + (kt & 1) * STAGE_B;
        const uint32_t stW = stA + SPLANE_B;

#pragma unroll
        for (int ks = 0; ks < 2; ks++) {
            const uint32_t ko = ks * 32;
            uint32_t ah[4][4];
#pragma unroll
            for (int mt = 0; mt < 4; mt++)
                LDSM4(ah[mt], stA + aoffm[mt] + ko);
            uint32_t bh[4][4];
#pragma unroll
            for (int np = 0; np < 4; np++)
                LDSM4(bh[np], stW + boffn[np] + ko);
#pragma unroll
            for (int nt = 0; nt < 8; nt++) {
                const int np = nt >> 1, g = nt & 1;
                uint32_t bhf[2] = {bh[np][g], bh[np][2 + g]};
#pragma unroll
                for (int mt = 0; mt < 4; mt++)
                    mma_fp16(acc[mt][nt], ah[mt], bhf);
            }
        }
        __syncthreads();
    }

    if (half_out) {
        // fused q/kv epilogue: whole CTA is on one side of the 2048 boundary
        __half* dst;
        int cbase, stride;
        float sc;
        if (n0 < kE) { dst = Chq;  cbase = n0;       stride = kE;   sc = QSCALE; }
        else         { dst = Chkv; cbase = n0 - kE;  stride = kKVN; sc = 1.0f;   }
#pragma unroll
        for (int mt = 0; mt < 4; mt++) {
            const int r = m0 + wm * 64 + mt * 16 + rq;
#pragma unroll
            for (int nt = 0; nt < 8; nt++) {
                const int c = cbase + wn * 64 + nt * 8 + (wc << 1);
                *(uint32_t*)&dst[(size_t)r * stride + c] =
                    pack_h2(acc[mt][nt][0] * sc, acc[mt][nt][1] * sc);
                *(uint32_t*)&dst[(size_t)(r + 8) * stride + c] =
                    pack_h2(acc[mt][nt][2] * sc, acc[mt][nt][3] * sc);
            }
        }
    } else {
#pragma unroll
        for (int mt = 0; mt < 4; mt++) {
            const int r = m0 + wm * 64 + mt * 16 + rq;
#pragma unroll
            for (int nt = 0; nt < 8; nt++) {
                const int c = n0 + wn * 64 + nt * 8 + (wc << 1);
                *(float2*)&Cf[(size_t)r * kE + c]       = make_float2(acc[mt][nt][0], acc[mt][nt][1]);
                *(float2*)&Cf[(size_t)(r + 8) * kE + c] = make_float2(acc[mt][nt][2], acc[mt][nt][3]);
            }
        }
    }
}

// ---------------------------------------------------------------------------
// Flash attention (causal, GQA), fp16 m16n8k16 — R15 proven version, untouched.
// ---------------------------------------------------------------------------
#define AQ_OFF 0                         // Qs: 2 heads * 64 * 144 = 18432
#define AK_OFF 18432                     // K stages: 2 * 9216
#define AV_OFF 36864                     // V stages: 2 * 9216
#define ATTN_SMEM 55296

__global__ __launch_bounds__(256) void attn_kernel(
        const __half* __restrict__ qh, const __half* __restrict__ kvh,
        __half* __restrict__ aoh) {
    extern __shared__ char smc[];
    const uint32_t sb = smem_u32(smc);

    const int tid  = threadIdx.x;
    const int lane = tid & 31;
    const int w    = tid >> 5;          // 0..7
    const int wg   = w >> 2;            // head sub-index 0/1
    const int wl   = w & 3;             // warp within head
    const int qb   = gridDim.x - 1 - blockIdx.x;   // LPT: heavy blocks first
    const int pidx = blockIdx.y;        // (b, head-pair)
    const int b    = pidx >> 4;
    const int hp   = pidx & 15;
    const int hq   = hp * 2 + wg;
    const int hkv  = hp >> 1;

    const uint32_t qsu = sb + AQ_OFF + wg * 9216;

    // ---- Load both heads' Q tiles: pure 16B copies (fp16, pre-scaled)
    {
        const int half  = tid >> 7;               // 0/1 -> head
        const int hrow  = (tid & 127) >> 3;       // 0..15
        const int hcol  = (tid & 7) * 8;          // halves, 0..56
        const int hqh   = hp * 2 + half;
        char* Qdst = smc + AQ_OFF + half * 9216;
#pragma unroll
        for (int p = 0; p < 4; p++) {
            int row = p * 16 + hrow;
            const uint4 v = *(const uint4*)
                &qh[((size_t)(b * kT + qb * 64 + row)) * kE + hqh * kHD + hcol];
            *(uint4*)(Qdst + row * 144 + hcol * 2) = v;
        }
    }

    // K/V fill via cp.async
    const int frow = tid >> 2;              // 0..63
    const int fsegh = (tid & 3) * 16;       // halves offset within row
    auto fill_kv = [&](int s, int j) {
        const __half* kg = kvh + ((size_t)(b * kT + j * 64 + frow)) * kKVN
                               + hkv * kHD + fsegh;
        const uint32_t stk = sb + AK_OFF + s * 9216 + frow * 144 + fsegh * 2;
        const uint32_t stv = sb + AV_OFF + s * 9216 + frow * 144 + fsegh * 2;
        cp16(stk,      kg);
        cp16(stk + 16, kg + 8);
        cp16(stv,      kg + 512);
        cp16(stv + 16, kg + 520);
    };

    float mrow0 = -INFINITY, mrow1 = -INFINITY;
    float lrow0 = 0.f, lrow1 = 0.f;
    float o[8][4];
#pragma unroll
    for (int nt = 0; nt < 8; nt++)
#pragma unroll
        for (int i = 0; i < 4; i++) o[nt][i] = 0.f;

    const int rloc = wl * 16 + (lane >> 2);   // warp's rows rloc, rloc+8 (0..63)

    // ldmatrix lane addresses
    const int lr8 = lane & 7;
    const int r8  = (lane >> 3) & 1;
    const int c4  = (lane >> 4) & 1;
    const uint32_t aoffQ = (uint32_t)((wl * 16 + lr8 + 8 * r8) * 144 + c4 * 16);
    uint32_t boffK[4];   // K: non-trans, [n][k]
#pragma unroll
    for (int np = 0; np < 4; np++)
        boffK[np] = (uint32_t)((np * 16 + lr8 + 8 * r8) * 144 + c4 * 16);
    uint32_t boffV[4];   // V: trans, [t][d]
#pragma unroll
    for (int np = 0; np < 4; np++)
        boffV[np] = (uint32_t)((lr8 + 8 * r8) * 144 + (np * 16 + 8 * c4) * 2);

    const int la = lane & 3;

    fill_kv(0, 0);
    CP_COMMIT();

    // Hoist Q fragments (loop-invariant)
    __syncthreads();
    uint32_t qa[4][4];
#pragma unroll
    for (int ks = 0; ks < 4; ks++)
        LDSM4(qa[ks], qsu + aoffQ + ks * 32);

    for (int j = 0; j <= qb; j++) {
        CP_WAIT(0);
        __syncthreads();                 // stage j&1 ready; other stage free
        if (j < qb) {
            fill_kv((j + 1) & 1, j + 1); // overlaps compute below
            CP_COMMIT();
        }

        const uint32_t ksu = sb + AK_OFF + (j & 1) * 9216;
        const uint32_t vsu = sb + AV_OFF + (j & 1) * 9216;

        // S = Q * K^T  (fp16 m16n8k16, 4 k-steps)
        float s[8][4];
#pragma unroll
        for (int nt = 0; nt < 8; nt++) { s[nt][0] = s[nt][1] = s[nt][2] = s[nt][3] = 0.f; }

#pragma unroll
        for (int ks = 0; ks < 4; ks++) {
            const uint32_t ko = ks * 32;
#pragma unroll
            for (int np = 0; np < 4; np++) {
                uint32_t kb[4];
                LDSM4(kb, ksu + boffK[np] + ko);
#pragma unroll
                for (int g = 0; g < 2; g++) {
                    uint32_t bb[2] = {kb[g], kb[2 + g]};
                    mma_fp16(s[2 * np + g], qa[ks], bb);
                }
            }
        }

        // Causal mask on the diagonal block
        if (j == qb) {
#pragma unroll
            for (int nt = 0; nt < 8; nt++) {
                int c0 = nt * 8 + (la << 1);
                if (c0     > rloc)     s[nt][0] = -INFINITY;
                if (c0 + 1 > rloc)     s[nt][1] = -INFINITY;
                if (c0     > rloc + 8) s[nt][2] = -INFINITY;
                if (c0 + 1 > rloc + 8) s[nt][3] = -INFINITY;
            }
        }

        // Online softmax (exp2 domain)
        float mx0 = -INFINITY, mx1 = -INFINITY;
#pragma unroll
        for (int nt = 0; nt < 8; nt++) {
            mx0 = fmaxf(mx0, fmaxf(s[nt][0], s[nt][1]));
            mx1 = fmaxf(mx1, fmaxf(s[nt][2], s[nt][3]));
        }
        mx0 = fmaxf(mx0, __shfl_xor_sync(0xffffffffu, mx0, 1));
        mx0 = fmaxf(mx0, __shfl_xor_sync(0xffffffffu, mx0, 2));
        mx1 = fmaxf(mx1, __shfl_xor_sync(0xffffffffu, mx1, 1));
        mx1 = fmaxf(mx1, __shfl_xor_sync(0xffffffffu, mx1, 2));

        float mnew0 = fmaxf(mrow0, mx0);
        float mnew1 = fmaxf(mrow1, mx1);
        float alpha0 = ex2(mrow0 - mnew0);
        float alpha1 = ex2(mrow1 - mnew1);
        mrow0 = mnew0; mrow1 = mnew1;

        float sum0 = 0.f, sum1 = 0.f;
#pragma unroll
        for (int nt = 0; nt < 8; nt++) {
            s[nt][0] = ex2(s[nt][0] - mnew0); sum0 += s[nt][0];
            s[nt][1] = ex2(s[nt][1] - mnew0); sum0 += s[nt][1];
            s[nt][2] = ex2(s[nt][2] - mnew1); sum1 += s[nt][2];
            s[nt][3] = ex2(s[nt][3] - mnew1); sum1 += s[nt][3];
        }
        sum0 += __shfl_xor_sync(0xffffffffu, sum0, 1);
        sum0 += __shfl_xor_sync(0xffffffffu, sum0, 2);
        sum1 += __shfl_xor_sync(0xffffffffu, sum1, 1);
        sum1 += __shfl_xor_sync(0xffffffffu, sum1, 2);

        lrow0 = lrow0 * alpha0 + sum0;
        lrow1 = lrow1 * alpha1 + sum1;

#pragma unroll
        for (int nt = 0; nt < 8; nt++) {
            o[nt][0] *= alpha0; o[nt][1] *= alpha0;
            o[nt][2] *= alpha1; o[nt][3] *= alpha1;
        }

        // O += P * V — P packed from S registers; V B-frags via ldmatrix.trans
#pragma unroll
        for (int ks = 0; ks < 4; ks++) {
            uint32_t a[4];
            a[0] = pack_h2(s[2*ks][0],   s[2*ks][1]);
            a[1] = pack_h2(s[2*ks][2],   s[2*ks][3]);
            a[2] = pack_h2(s[2*ks+1][0], s[2*ks+1][1]);
            a[3] = pack_h2(s[2*ks+1][2], s[2*ks+1][3]);
            const uint32_t vk = vsu + ks * 16 * 144;
#pragma unroll
            for (int np = 0; np < 4; np++) {
                uint32_t vb[4];
                LDSM4T(vb, vk + boffV[np]);
                mma_fp16(o[2 * np],     a, vb);       // n-block np*16..+7
                mma_fp16(o[2 * np + 1], a, vb + 2);   // n-block np*16+8..+15
            }
        }
        // no trailing barrier: top-of-loop barrier guards stage recycling
    }

    // Normalize and emit fp16 plane for the O-projection
    float inv0 = 1.f / lrow0;
    float inv1 = 1.f / lrow1;
    size_t r0 = (size_t)(b * kT + qb * 64 + rloc) * kE + hq * kHD;
    size_t r1 = (size_t)(b * kT + qb * 64 + rloc + 8) * kE + hq * kHD;
#pragma unroll
    for (int nt = 0; nt < 8; nt++) {
        int c = nt * 8 + (la << 1);
        *(uint32_t*)&aoh[r0 + c] = pack_h2(o[nt][0] * inv0, o[nt][1] * inv0);
        *(uint32_t*)&aoh[r1 + c] = pack_h2(o[nt][2] * inv1, o[nt][3] * inv1);
    }
}

// ---------------------------------------------------------------------------
// Launch
// ---------------------------------------------------------------------------
extern "C" void kernel_launch(void* const* d_in, const int* in_sizes, int n_in,
                              void* d_out, int out_size) {
    (void)in_sizes; (void)n_in; (void)out_size;
    const float* x   = (const float*)d_in[0];
    const float* Wq  = (const float*)d_in[1];
    const float* Wkv = (const float*)d_in[2];
    const float* Wo  = (const float*)d_in[3];
    float* out = (float*)d_out;

    __half *qh, *kvh, *xh, *wch, *woh, *aoh;
    cudaGetSymbolAddress((void**)&qh,  g_qh);
    cudaGetSymbolAddress((void**)&kvh, g_kvh);
    cudaGetSymbolAddress((void**)&xh,  g_xh);
    cudaGetSymbolAddress((void**)&wch, g_wch);
    cudaGetSymbolAddress((void**)&woh, g_woh);
    cudaGetSymbolAddress((void**)&aoh, g_aoh);

    cudaFuncSetAttribute(gemm_f16,
                         cudaFuncAttributeMaxDynamicSharedMemorySize, GEMM_SMEM);
    cudaFuncSetAttribute(attn_kernel,
                         cudaFuncAttributeMaxDynamicSharedMemorySize, ATTN_SMEM);

    // One fused cast launch (x -> xh; Wq+Wkv -> wch; Wo -> woh)
    cast_all<<<(C4 + 255) / 256, 256>>>(x, Wq, Wkv, Wo, xh, wch, woh);

    // Fused q+kv projection: one N=3072 GEMM, epilogue routes per side
    gemm_f16<<<dim3(kNF / 128, kM / 128), 128, GEMM_SMEM>>>(
        xh, wch, nullptr, qh, kvh, kE, 1);

    // Attention (LPT order, double-buffered K/V, hoisted Q frags)
    attn_kernel<<<dim3(kT / 64, kB * kHQ / 2), 256, ATTN_SMEM>>>(qh, kvh, aoh);

    // O-projection (fp32 out)
    gemm_f16<<<dim3(kE / 128, kM / 128), 128, GEMM_SMEM>>>(
        aoh, woh, out, nullptr, nullptr, kE, 0);
}

// round 17
// speedup vs baseline: 1.2559x; 1.0264x over previous
#include <cuda_runtime.h>
#include <cuda_fp16.h>
#include <math.h>
#include <stdint.h>

// Problem constants
#define kE   2048
#define kHQ  32
#define kHKV 8
#define kHD  64
#define kB   2
#define kT   2048
#define kM   (kB * kT)          // 4096 rows (B*T)
#define kKVN (2 * kHKV * kHD)   // 1024
#define kNF  (kE + kKVN)        // 3072 fused q+kv output cols

#define QSCALE 0.1803368801111204f   // 0.125 * log2(e)

// ---------------------------------------------------------------------------
// Device-global scratch
// ---------------------------------------------------------------------------
__device__ __half g_qh[kM * kE];     // q projection, fp16, pre-scaled by QSCALE
__device__ __half g_kvh[kM * kKVN];  // kv projection fp16: k [0,512), v [512,1024)
__device__ __half g_xh[kM * kE];
__device__ __half g_wch[kNF * kE];   // fused weights: Wq rows 0..2047, Wkv rows 2048..3071
__device__ __half g_woh[kE * kE];
__device__ __half g_aoh[kM * kE];    // attention out, fp16

// ---------------------------------------------------------------------------
// Helpers
// ---------------------------------------------------------------------------
__device__ __forceinline__ uint32_t smem_u32(const void* p) {
    uint32_t a;
    asm("{ .reg .u64 t; cvta.to.shared.u64 t, %1; cvt.u32.u64 %0, t; }"
        : "=r"(a) : "l"(p));
    return a;
}

__device__ __forceinline__ void cp16(uint32_t saddr, const void* g) {
    asm volatile("cp.async.cg.shared.global [%0], [%1], 16;"
                 :: "r"(saddr), "l"(g) : "memory");
}
#define CP_COMMIT()  asm volatile("cp.async.commit_group;" ::: "memory")
#define CP_WAIT(n)   asm volatile("cp.async.wait_group %0;" :: "n"(n) : "memory")

#define LDSM4(r, addr)                                                        \
    asm volatile("ldmatrix.sync.aligned.m8n8.x4.shared.b16 {%0,%1,%2,%3}, [%4];" \
        : "=r"((r)[0]), "=r"((r)[1]), "=r"((r)[2]), "=r"((r)[3]) : "r"(addr))

#define LDSM4T(r, addr)                                                       \
    asm volatile("ldmatrix.sync.aligned.m8n8.x4.trans.shared.b16 {%0,%1,%2,%3}, [%4];" \
        : "=r"((r)[0]), "=r"((r)[1]), "=r"((r)[2]), "=r"((r)[3]) : "r"(addr))

// fp16 tensor op: D(16x8,f32) += A(16x16,f16) * B(16x8,f16)
__device__ __forceinline__ void mma_fp16(float* d, const uint32_t* a, const uint32_t* b) {
    asm volatile(
        "mma.sync.aligned.m16n8k16.row.col.f32.f16.f16.f32 "
        "{%0,%1,%2,%3},{%4,%5,%6,%7},{%8,%9},{%0,%1,%2,%3};\n"
        : "+f"(d[0]), "+f"(d[1]), "+f"(d[2]), "+f"(d[3])
        : "r"(a[0]), "r"(a[1]), "r"(a[2]), "r"(a[3]), "r"(b[0]), "r"(b[1]));
}

__device__ __forceinline__ uint32_t pack_h2(float a, float b) {
    __half2 h = __floats2half2_rn(a, b);
    return *reinterpret_cast<uint32_t*>(&h);
}

__device__ __forceinline__ float ex2(float x) {
    float r;
    asm("ex2.approx.ftz.f32 %0, %1;" : "=f"(r) : "f"(x));
    return r;
}

// ---------------------------------------------------------------------------
// Fused fp32 -> fp16 cast: x -> xh; Wq,Wkv -> combined wch; Wo -> woh
// ---------------------------------------------------------------------------
#define C1 2097152              // x       float4 count
#define C2 (C1 + 1048576)       // + Wq
#define C3 (C2 + 524288)        // + Wkv
#define C4 (C3 + 1048576)       // + Wo

__global__ __launch_bounds__(256) void cast_all(
        const float* __restrict__ x,  const float* __restrict__ wq,
        const float* __restrict__ wkv, const float* __restrict__ wo,
        __half* __restrict__ xh, __half* __restrict__ wch,
        __half* __restrict__ woh) {
    int i = blockIdx.x * 256 + threadIdx.x;
    if (i >= C4) return;
    const float* src; __half* dst; int off;
    if (i < C1)      { src = x;   dst = xh;  off = i; }
    else if (i < C2) { src = wq;  dst = wch; off = i - C1; }
    else if (i < C3) { src = wkv; dst = wch; off = i - C2; }
    else             { src = wo;  dst = woh; off = i - C3; }
    float4 v = ((const float4*)src)[off];
    uint32_t* hp;
    if (i >= C2 && i < C3) {
        hp = (uint32_t*)(wch + (size_t)kE * kE) + 2 * (size_t)off;
    } else {
        hp = (uint32_t*)dst + 2 * (size_t)off;
    }
    hp[0] = pack_h2(v.x, v.y);
    hp[1] = pack_h2(v.z, v.w);
}

// ---------------------------------------------------------------------------
// GEMM: C = A[M,K] * W[N,K]^T, plain fp16.
// CTA 128x128, K-tile 32, 4 warps with 64x64 warp tiles (2x2 grid).
// 3-stage cp.async ring, ONE barrier per k-tile; all fragments for both
// k16-steps loaded up front (16 LDSM -> 64 independent MMAs).
// Row stride 80B (conflict-free LDSM). R12-proven coalesced staging.
// mode 1 (fused q/kv): n0<2048 -> qh (QSCALE, stride kE), else kvh (1, kKVN).
// mode 0: fp32 out, stride kE.
// ---------------------------------------------------------------------------
#define SPLANE_W 2560                       // 128 * 20 u32 words
#define SPLANE_B (SPLANE_W * 4)             // 10240 bytes
#define STAGE_B  (2 * SPLANE_B)             // A, W
#define GEMM_SMEM (3 * STAGE_B)             // 61440 bytes (3 stages)

__global__ __launch_bounds__(128) void gemm_f16(
        const __half* __restrict__ Ah, const __half* __restrict__ Whi,
        float* __restrict__ Cf, __half* __restrict__ Chq, __half* __restrict__ Chkv,
        int K, int half_out) {
    extern __shared__ char smem[];
    const uint32_t sbase = smem_u32(smem);

    const int tid  = threadIdx.x;
    const int lane = tid & 31;
    const int wid  = tid >> 5;        // 0..3
    const int wm   = wid >> 1;        // 0..1 (64 rows each)
    const int wn   = wid & 1;         // 0..1 (64 cols each)
    const int m0   = blockIdx.y * 128;
    const int n0   = blockIdx.x * 128;

    float acc[4][8][4];
#pragma unroll
    for (int i = 0; i < 4; i++)
#pragma unroll
        for (int j = 0; j < 8; j++)
#pragma unroll
            for (int k = 0; k < 4; k++) acc[i][j][k] = 0.f;

    const size_t gs = (size_t)K * 2;  // bytes per global row
    const int crow  = tid >> 1;       // 0..63
    const int cbo   = (tid & 1) << 5; // 0 or 32 bytes

    const char* pA = (const char*)Ah;
    const char* pW = (const char*)Whi;

    const int NKT = K >> 5;

    // R12-proven coalesced staging (each thread: 2 rows x 2 chunks per matrix)
    auto copy_tile = [&](int s, int kt) {
#pragma unroll
        for (int h = 0; h < 2; h++) {
            const int row = h * 64 + crow;
            const uint32_t st = sbase + s * STAGE_B + row * 80 + cbo;
            const size_t goA = (size_t)(m0 + row) * gs + (size_t)kt * 64 + cbo;
            const size_t goW = (size_t)(n0 + row) * gs + (size_t)kt * 64 + cbo;
            cp16(st,                 pA + goA);
            cp16(st + 16,            pA + goA + 16);
            cp16(st + SPLANE_B,      pW + goW);
            cp16(st + SPLANE_B + 16, pW + goW + 16);
        }
    };

    copy_tile(0, 0);
    CP_COMMIT();
    if (NKT > 1) { copy_tile(1, 1); CP_COMMIT(); }

    // ldmatrix lane-address components
    const int lr8 = lane & 7;
    const int r8  = (lane >> 3) & 1;
    const int c4  = (lane >> 4) & 1;
    uint32_t aoffm[4], boffn[4];
#pragma unroll
    for (int mt = 0; mt < 4; mt++)
        aoffm[mt] = (uint32_t)((wm * 64 + mt * 16 + lr8 + 8 * r8) * 80 + c4 * 16);
#pragma unroll
    for (int np = 0; np < 4; np++)
        boffn[np] = (uint32_t)((wn * 64 + np * 16 + lr8 + 8 * r8) * 80 + c4 * 16);

    const int rq = lane >> 2;
    const int wc = lane & 3;

    int st3 = 0;   // stage index of k-tile kt
    for (int kt = 0; kt < NKT; kt++) {
        if (kt + 1 < NKT) CP_WAIT(1); else CP_WAIT(0);
        __syncthreads();   // stage st3 ready; all warps past kt-1 reads
        if (kt + 2 < NKT) {
            int s2 = st3 + 2; if (s2 >= 3) s2 -= 3;
            copy_tile(s2, kt + 2);    // overlaps compute below
            CP_COMMIT();
        }

        const uint32_t stA = sbase + st3 * STAGE_B;
        const uint32_t stW = stA + SPLANE_B;

        // Load ALL fragments for both k16-steps (16 LDSM), then 64 MMAs
        uint32_t ah[2][4][4], bh[2][4][4];
#pragma unroll
        for (int ks = 0; ks < 2; ks++) {
            const uint32_t ko = ks * 32;
#pragma unroll
            for (int mt = 0; mt < 4; mt++)
                LDSM4(ah[ks][mt], stA + aoffm[mt] + ko);
#pragma unroll
            for (int np = 0; np < 4; np++)
                LDSM4(bh[ks][np], stW + boffn[np] + ko);
        }
#pragma unroll
        for (int ks = 0; ks < 2; ks++) {
#pragma unroll
            for (int nt = 0; nt < 8; nt++) {
                const int np = nt >> 1, g = nt & 1;
                uint32_t bhf[2] = {bh[ks][np][g], bh[ks][np][2 + g]};
#pragma unroll
                for (int mt = 0; mt < 4; mt++)
                    mma_fp16(acc[mt][nt], ah[ks][mt], bhf);
            }
        }
        st3++; if (st3 == 3) st3 = 0;
        // no trailing barrier: 3-stage ring + top barrier cover the hazard
    }

    if (half_out) {
        // fused q/kv epilogue: whole CTA is on one side of the 2048 boundary
        __half* dst;
        int cbase, stride;
        float sc;
        if (n0 < kE) { dst = Chq;  cbase = n0;       stride = kE;   sc = QSCALE; }
        else         { dst = Chkv; cbase = n0 - kE;  stride = kKVN; sc = 1.0f;   }
#pragma unroll
        for (int mt = 0; mt < 4; mt++) {
            const int r = m0 + wm * 64 + mt * 16 + rq;
#pragma unroll
            for (int nt = 0; nt < 8; nt++) {
                const int c = cbase + wn * 64 + nt * 8 + (wc << 1);
                *(uint32_t*)&dst[(size_t)r * stride + c] =
                    pack_h2(acc[mt][nt][0] * sc, acc[mt][nt][1] * sc);
                *(uint32_t*)&dst[(size_t)(r + 8) * stride + c] =
                    pack_h2(acc[mt][nt][2] * sc, acc[mt][nt][3] * sc);
            }
        }
    } else {
#pragma unroll
        for (int mt = 0; mt < 4; mt++) {
            const int r = m0 + wm * 64 + mt * 16 + rq;
#pragma unroll
            for (int nt = 0; nt < 8; nt++) {
                const int c = n0 + wn * 64 + nt * 8 + (wc << 1);
                *(float2*)&Cf[(size_t)r * kE + c]       = make_float2(acc[mt][nt][0], acc[mt][nt][1]);
                *(float2*)&Cf[(size_t)(r + 8) * kE + c] = make_float2(acc[mt][nt][2], acc[mt][nt][3]);
            }
        }
    }
}

// ---------------------------------------------------------------------------
// Flash attention (causal, GQA), fp16 m16n8k16 — proven version, untouched.
// ---------------------------------------------------------------------------
#define AQ_OFF 0                         // Qs: 2 heads * 64 * 144 = 18432
#define AK_OFF 18432                     // K stages: 2 * 9216
#define AV_OFF 36864                     // V stages: 2 * 9216
#define ATTN_SMEM 55296

__global__ __launch_bounds__(256) void attn_kernel(
        const __half* __restrict__ qh, const __half* __restrict__ kvh,
        __half* __restrict__ aoh) {
    extern __shared__ char smc[];
    const uint32_t sb = smem_u32(smc);

    const int tid  = threadIdx.x;
    const int lane = tid & 31;
    const int w    = tid >> 5;          // 0..7
    const int wg   = w >> 2;            // head sub-index 0/1
    const int wl   = w & 3;             // warp within head
    const int qb   = gridDim.x - 1 - blockIdx.x;   // LPT: heavy blocks first
    const int pidx = blockIdx.y;        // (b, head-pair)
    const int b    = pidx >> 4;
    const int hp   = pidx & 15;
    const int hq   = hp * 2 + wg;
    const int hkv  = hp >> 1;

    const uint32_t qsu = sb + AQ_OFF + wg * 9216;

    // ---- Load both heads' Q tiles: pure 16B copies (fp16, pre-scaled)
    {
        const int half  = tid >> 7;               // 0/1 -> head
        const int hrow  = (tid & 127) >> 3;       // 0..15
        const int hcol  = (tid & 7) * 8;          // halves, 0..56
        const int hqh   = hp * 2 + half;
        char* Qdst = smc + AQ_OFF + half * 9216;
#pragma unroll
        for (int p = 0; p < 4; p++) {
            int row = p * 16 + hrow;
            const uint4 v = *(const uint4*)
                &qh[((size_t)(b * kT + qb * 64 + row)) * kE + hqh * kHD + hcol];
            *(uint4*)(Qdst + row * 144 + hcol * 2) = v;
        }
    }

    // K/V fill via cp.async
    const int frow = tid >> 2;              // 0..63
    const int fsegh = (tid & 3) * 16;       // halves offset within row
    auto fill_kv = [&](int s, int j) {
        const __half* kg = kvh + ((size_t)(b * kT + j * 64 + frow)) * kKVN
                               + hkv * kHD + fsegh;
        const uint32_t stk = sb + AK_OFF + s * 9216 + frow * 144 + fsegh * 2;
        const uint32_t stv = sb + AV_OFF + s * 9216 + frow * 144 + fsegh * 2;
        cp16(stk,      kg);
        cp16(stk + 16, kg + 8);
        cp16(stv,      kg + 512);
        cp16(stv + 16, kg + 520);
    };

    float mrow0 = -INFINITY, mrow1 = -INFINITY;
    float lrow0 = 0.f, lrow1 = 0.f;
    float o[8][4];
#pragma unroll
    for (int nt = 0; nt < 8; nt++)
#pragma unroll
        for (int i = 0; i < 4; i++) o[nt][i] = 0.f;

    const int rloc = wl * 16 + (lane >> 2);   // warp's rows rloc, rloc+8 (0..63)

    // ldmatrix lane addresses
    const int lr8 = lane & 7;
    const int r8  = (lane >> 3) & 1;
    const int c4  = (lane >> 4) & 1;
    const uint32_t aoffQ = (uint32_t)((wl * 16 + lr8 + 8 * r8) * 144 + c4 * 16);
    uint32_t boffK[4];   // K: non-trans, [n][k]
#pragma unroll
    for (int np = 0; np < 4; np++)
        boffK[np] = (uint32_t)((np * 16 + lr8 + 8 * r8) * 144 + c4 * 16);
    uint32_t boffV[4];   // V: trans, [t][d]
#pragma unroll
    for (int np = 0; np < 4; np++)
        boffV[np] = (uint32_t)((lr8 + 8 * r8) * 144 + (np * 16 + 8 * c4) * 2);

    const int la = lane & 3;

    fill_kv(0, 0);
    CP_COMMIT();

    // Hoist Q fragments (loop-invariant)
    __syncthreads();
    uint32_t qa[4][4];
#pragma unroll
    for (int ks = 0; ks < 4; ks++)
        LDSM4(qa[ks], qsu + aoffQ + ks * 32);

    for (int j = 0; j <= qb; j++) {
        CP_WAIT(0);
        __syncthreads();                 // stage j&1 ready; other stage free
        if (j < qb) {
            fill_kv((j + 1) & 1, j + 1); // overlaps compute below
            CP_COMMIT();
        }

        const uint32_t ksu = sb + AK_OFF + (j & 1) * 9216;
        const uint32_t vsu = sb + AV_OFF + (j & 1) * 9216;

        // S = Q * K^T  (fp16 m16n8k16, 4 k-steps)
        float s[8][4];
#pragma unroll
        for (int nt = 0; nt < 8; nt++) { s[nt][0] = s[nt][1] = s[nt][2] = s[nt][3] = 0.f; }

#pragma unroll
        for (int ks = 0; ks < 4; ks++) {
            const uint32_t ko = ks * 32;
#pragma unroll
            for (int np = 0; np < 4; np++) {
                uint32_t kb[4];
                LDSM4(kb, ksu + boffK[np] + ko);
#pragma unroll
                for (int g = 0; g < 2; g++) {
                    uint32_t bb[2] = {kb[g], kb[2 + g]};
                    mma_fp16(s[2 * np + g], qa[ks], bb);
                }
            }
        }

        // Causal mask on the diagonal block
        if (j == qb) {
#pragma unroll
            for (int nt = 0; nt < 8; nt++) {
                int c0 = nt * 8 + (la << 1);
                if (c0     > rloc)     s[nt][0] = -INFINITY;
                if (c0 + 1 > rloc)     s[nt][1] = -INFINITY;
                if (c0     > rloc + 8) s[nt][2] = -INFINITY;
                if (c0 + 1 > rloc + 8) s[nt][3] = -INFINITY;
            }
        }

        // Online softmax (exp2 domain)
        float mx0 = -INFINITY, mx1 = -INFINITY;
#pragma unroll
        for (int nt = 0; nt < 8; nt++) {
            mx0 = fmaxf(mx0, fmaxf(s[nt][0], s[nt][1]));
            mx1 = fmaxf(mx1, fmaxf(s[nt][2], s[nt][3]));
        }
        mx0 = fmaxf(mx0, __shfl_xor_sync(0xffffffffu, mx0, 1));
        mx0 = fmaxf(mx0, __shfl_xor_sync(0xffffffffu, mx0, 2));
        mx1 = fmaxf(mx1, __shfl_xor_sync(0xffffffffu, mx1, 1));
        mx1 = fmaxf(mx1, __shfl_xor_sync(0xffffffffu, mx1, 2));

        float mnew0 = fmaxf(mrow0, mx0);
        float mnew1 = fmaxf(mrow1, mx1);
        float alpha0 = ex2(mrow0 - mnew0);
        float alpha1 = ex2(mrow1 - mnew1);
        mrow0 = mnew0; mrow1 = mnew1;

        float sum0 = 0.f, sum1 = 0.f;
#pragma unroll
        for (int nt = 0; nt < 8; nt++) {
            s[nt][0] = ex2(s[nt][0] - mnew0); sum0 += s[nt][0];
            s[nt][1] = ex2(s[nt][1] - mnew0); sum0 += s[nt][1];
            s[nt][2] = ex2(s[nt][2] - mnew1); sum1 += s[nt][2];
            s[nt][3] = ex2(s[nt][3] - mnew1); sum1 += s[nt][3];
        }
        sum0 += __shfl_xor_sync(0xffffffffu, sum0, 1);
        sum0 += __shfl_xor_sync(0xffffffffu, sum0, 2);
        sum1 += __shfl_xor_sync(0xffffffffu, sum1, 1);
        sum1 += __shfl_xor_sync(0xffffffffu, sum1, 2);

        lrow0 = lrow0 * alpha0 + sum0;
        lrow1 = lrow1 * alpha1 + sum1;

#pragma unroll
        for (int nt = 0; nt < 8; nt++) {
            o[nt][0] *= alpha0; o[nt][1] *= alpha0;
            o[nt][2] *= alpha1; o[nt][3] *= alpha1;
        }

        // O += P * V — P packed from S registers; V B-frags via ldmatrix.trans
#pragma unroll
        for (int ks = 0; ks < 4; ks++) {
            uint32_t a[4];
            a[0] = pack_h2(s[2*ks][0],   s[2*ks][1]);
            a[1] = pack_h2(s[2*ks][2],   s[2*ks][3]);
            a[2] = pack_h2(s[2*ks+1][0], s[2*ks+1][1]);
            a[3] = pack_h2(s[2*ks+1][2], s[2*ks+1][3]);
            const uint32_t vk = vsu + ks * 16 * 144;
#pragma unroll
            for (int np = 0; np < 4; np++) {
                uint32_t vb[4];
                LDSM4T(vb, vk + boffV[np]);
                mma_fp16(o[2 * np],     a, vb);       // n-block np*16..+7
                mma_fp16(o[2 * np + 1], a, vb + 2);   // n-block np*16+8..+15
            }
        }
        // no trailing barrier: top-of-loop barrier guards stage recycling
    }

    // Normalize and emit fp16 plane for the O-projection
    float inv0 = 1.f / lrow0;
    float inv1 = 1.f / lrow1;
    size_t r0 = (size_t)(b * kT + qb * 64 + rloc) * kE + hq * kHD;
    size_t r1 = (size_t)(b * kT + qb * 64 + rloc + 8) * kE + hq * kHD;
#pragma unroll
    for (int nt = 0; nt < 8; nt++) {
        int c = nt * 8 + (la << 1);
        *(uint32_t*)&aoh[r0 + c] = pack_h2(o[nt][0] * inv0, o[nt][1] * inv0);
        *(uint32_t*)&aoh[r1 + c] = pack_h2(o[nt][2] * inv1, o[nt][3] * inv1);
    }
}

// ---------------------------------------------------------------------------
// Launch
// ---------------------------------------------------------------------------
extern "C" void kernel_launch(void* const* d_in, const int* in_sizes, int n_in,
                              void* d_out, int out_size) {
    (void)in_sizes; (void)n_in; (void)out_size;
    const float* x   = (const float*)d_in[0];
    const float* Wq  = (const float*)d_in[1];
    const float* Wkv = (const float*)d_in[2];
    const float* Wo  = (const float*)d_in[3];
    float* out = (float*)d_out;

    __half *qh, *kvh, *xh, *wch, *woh, *aoh;
    cudaGetSymbolAddress((void**)&qh,  g_qh);
    cudaGetSymbolAddress((void**)&kvh, g_kvh);
    cudaGetSymbolAddress((void**)&xh,  g_xh);
    cudaGetSymbolAddress((void**)&wch, g_wch);
    cudaGetSymbolAddress((void**)&woh, g_woh);
    cudaGetSymbolAddress((void**)&aoh, g_aoh);

    cudaFuncSetAttribute(gemm_f16,
                         cudaFuncAttributeMaxDynamicSharedMemorySize, GEMM_SMEM);
    cudaFuncSetAttribute(attn_kernel,
                         cudaFuncAttributeMaxDynamicSharedMemorySize, ATTN_SMEM);

    // One fused cast launch (x -> xh; Wq+Wkv -> wch; Wo -> woh)
    cast_all<<<(C4 + 255) / 256, 256>>>(x, Wq, Wkv, Wo, xh, wch, woh);

    // Fused q+kv projection: one N=3072 GEMM, epilogue routes per side
    gemm_f16<<<dim3(kNF / 128, kM / 128), 128, GEMM_SMEM>>>(
        xh, wch, nullptr, qh, kvh, kE, 1);

    // Attention (LPT order, double-buffered K/V, hoisted Q frags)
    attn_kernel<<<dim3(kT / 64, kB * kHQ / 2), 256, ATTN_SMEM>>>(qh, kvh, aoh);

    // O-projection (fp32 out)
    gemm_f16<<<dim3(kE / 128, kM / 128), 128, GEMM_SMEM>>>(
        aoh, woh, out, nullptr, nullptr, kE, 0);
}